// round 1
// baseline (speedup 1.0000x reference)
#include <cuda_runtime.h>
#include <math.h>

#define B_ 4
#define S_ 2048
#define E_ 1024
#define H_ 4
#define D_ 256
#define BH_ 16
#define MSZ (B_*S_*E_)

// ---- scratch (device globals; no runtime allocation allowed) ----
__device__ float g_Q[MSZ];
__device__ float g_K[MSZ];
__device__ float g_V[MSZ];
__device__ float g_SQ[MSZ];
__device__ float g_SK[MSZ];
__device__ float g_AO[MSZ];
__device__ float g_U[MSZ];
__device__ float g_P[(size_t)BH_*S_*S_];
__device__ float g_Zq[BH_*S_];
__device__ float g_Zk[BH_*S_];

#define BM 128
#define BN 128
#define BK 16

enum { MODE_PLAIN=0, MODE_SIG=1, MODE_BIAS=2, MODE_AMEM=3, MODE_DELTA=4 };

// Generic 128x128x16 fp32 GEMM, C = A@B, row-major, batched over blockIdx.z
// with (b,h)-decomposed pointer offsets. Fused epilogues via `mode`.
__global__ __launch_bounds__(256,2) void sgemm_nn(
    const float* __restrict__ A, const float* __restrict__ Bm, float* __restrict__ C,
    float* __restrict__ C2, const float* __restrict__ bias,
    const float* __restrict__ rowdiv, const float* __restrict__ mixbase,
    const float* __restrict__ betas,
    int M, int N, int K, int lda, int ldb, int ldc,
    long sAb, long sAh, long sBb, long sBh, long sCb, long sCh,
    int mode, int causal)
{
    __shared__ float As[BK][BM+4];
    __shared__ float Bs[BK][BN+4];
    int z = blockIdx.z;
    int bb = z / H_, hh = z % H_;
    A  += (long)bb*sAb + (long)hh*sAh;
    Bm += (long)bb*sBb + (long)hh*sBh;
    long coff = (long)bb*sCb + (long)hh*sCh;
    float* Cp = C + coff;
    const float* mix = mixbase ? (mixbase + coff) : (const float*)0;
    float* C2p = C2 ? (C2 + coff) : (float*)0;

    int m0 = blockIdx.y*BM, n0 = blockIdx.x*BN;
    int Keff = K;
    if (causal) { int kl = m0 + BM; Keff = kl < K ? kl : K; }
    int tid = threadIdx.x;
    int tx = tid & 15, ty = tid >> 4;

    float acc[8][8];
    #pragma unroll
    for (int i=0;i<8;i++)
        #pragma unroll
        for (int j=0;j<8;j++) acc[i][j]=0.f;

    for (int k0=0; k0<Keff; k0+=BK) {
        #pragma unroll
        for (int q=0;q<2;q++){
            int f = tid*2+q;
            int row = f>>2, ch = f&3;
            float4 v = *(const float4*)(A + (long)(m0+row)*lda + (k0 + ch*4));
            As[ch*4+0][row]=v.x; As[ch*4+1][row]=v.y;
            As[ch*4+2][row]=v.z; As[ch*4+3][row]=v.w;
        }
        #pragma unroll
        for (int q=0;q<2;q++){
            int f = tid*2+q;
            int kc = f>>5, ch = f&31;
            float4 v = *(const float4*)(Bm + (long)(k0+kc)*ldb + (n0 + ch*4));
            *(float4*)&Bs[kc][ch*4] = v;
        }
        __syncthreads();
        #pragma unroll
        for (int kc=0;kc<BK;kc++){
            float a[8], b[8];
            *(float4*)&a[0] = *(const float4*)&As[kc][ty*8];
            *(float4*)&a[4] = *(const float4*)&As[kc][ty*8+4];
            *(float4*)&b[0] = *(const float4*)&Bs[kc][tx*8];
            *(float4*)&b[4] = *(const float4*)&Bs[kc][tx*8+4];
            #pragma unroll
            for (int i=0;i<8;i++)
                #pragma unroll
                for (int j=0;j<8;j++) acc[i][j] = fmaf(a[i], b[j], acc[i][j]);
        }
        __syncthreads();
    }

    float gate = 0.f;
    if (mode==MODE_AMEM) gate = 1.f/(1.f+expf(-betas[hh]));

    #pragma unroll
    for (int i=0;i<8;i++){
        int r = m0 + ty*8 + i;
        float rinv = 0.f;
        if (mode==MODE_AMEM || mode==MODE_DELTA)
            rinv = 1.f/(rowdiv[(long)z*S_ + r] + 1e-6f);
        #pragma unroll
        for (int j=0;j<8;j++){
            int c = n0 + tx*8 + j;
            long idx = (long)r*ldc + c;
            float v = acc[i][j];
            if (mode==MODE_PLAIN)      Cp[idx]=v;
            else if (mode==MODE_SIG) { Cp[idx]=v; C2p[idx] = v>0.f ? v+1.f : expf(v); }
            else if (mode==MODE_BIAS)  Cp[idx]=v + bias[c];
            else if (mode==MODE_AMEM)  Cp[idx] = gate*(v*rinv) + (1.f-gate)*mix[idx];
            else                       Cp[idx] = mix[idx] - v*rinv;
        }
    }
}

// Scores = Q @ K^T per (b,h) with causal tile skip (upper-triangle tiles never
// written; they are never read because softmax zero-pads and PV K-limits).
__global__ __launch_bounds__(256,2) void scores_kernel(
    const float* __restrict__ Q, const float* __restrict__ Km, float* __restrict__ P)
{
    int z = blockIdx.z;
    int m0 = blockIdx.y*BM, n0 = blockIdx.x*BN;
    if (n0 > m0) return;
    const float* Aq = Q + (long)(z/H_)*S_*E_ + (z%H_)*D_;
    const float* Bk = Km + (long)(z/H_)*S_*E_ + (z%H_)*D_;
    float* Cp = P + (long)z*S_*S_;

    __shared__ float As[BK][BM+4];
    __shared__ float Bs[BK][BN+4];
    int tid = threadIdx.x;
    int tx = tid & 15, ty = tid >> 4;

    float acc[8][8];
    #pragma unroll
    for (int i=0;i<8;i++)
        #pragma unroll
        for (int j=0;j<8;j++) acc[i][j]=0.f;

    for (int k0=0; k0<D_; k0+=BK) {
        #pragma unroll
        for (int q=0;q<2;q++){
            int f = tid*2+q;
            int row = f>>2, ch = f&3;
            float4 v = *(const float4*)(Aq + (long)(m0+row)*E_ + (k0 + ch*4));
            As[ch*4+0][row]=v.x; As[ch*4+1][row]=v.y;
            As[ch*4+2][row]=v.z; As[ch*4+3][row]=v.w;
        }
        #pragma unroll
        for (int q=0;q<2;q++){
            int f = tid*2+q;
            int row = f>>2, ch = f&3;
            float4 v = *(const float4*)(Bk + (long)(n0+row)*E_ + (k0 + ch*4));
            Bs[ch*4+0][row]=v.x; Bs[ch*4+1][row]=v.y;
            Bs[ch*4+2][row]=v.z; Bs[ch*4+3][row]=v.w;
        }
        __syncthreads();
        #pragma unroll
        for (int kc=0;kc<BK;kc++){
            float a[8], b[8];
            *(float4*)&a[0] = *(const float4*)&As[kc][ty*8];
            *(float4*)&a[4] = *(const float4*)&As[kc][ty*8+4];
            *(float4*)&b[0] = *(const float4*)&Bs[kc][tx*8];
            *(float4*)&b[4] = *(const float4*)&Bs[kc][tx*8+4];
            #pragma unroll
            for (int i=0;i<8;i++)
                #pragma unroll
                for (int j=0;j<8;j++) acc[i][j] = fmaf(a[i], b[j], acc[i][j]);
        }
        __syncthreads();
    }
    #pragma unroll
    for (int i=0;i<8;i++){
        long r = m0 + ty*8 + i;
        #pragma unroll
        for (int j=0;j<8;j++)
            Cp[r*S_ + (n0 + tx*8 + j)] = acc[i][j];
    }
}

// Row-wise causal softmax; zeroes pad region up to the next 128 boundary so
// PV can read [0, m0+128) without masking.
__global__ void softmax_kernel(float* __restrict__ P)
{
    int i = blockIdx.x, z = blockIdx.y, tid = threadIdx.x;
    float* row = P + ((long)z*S_ + i)*S_;
    int len = i + 1;
    __shared__ float sh[8];

    float m = -3.4e38f;
    for (int j=tid; j<len; j+=256) m = fmaxf(m, row[j]);
    #pragma unroll
    for (int o=16;o;o>>=1) m = fmaxf(m, __shfl_xor_sync(0xffffffffu, m, o));
    if ((tid&31)==0) sh[tid>>5] = m;
    __syncthreads();
    m = sh[0];
    #pragma unroll
    for (int w=1;w<8;w++) m = fmaxf(m, sh[w]);
    __syncthreads();

    float s = 0.f;
    for (int j=tid; j<len; j+=256) s += expf(row[j]-m);
    #pragma unroll
    for (int o=16;o;o>>=1) s += __shfl_xor_sync(0xffffffffu, s, o);
    if ((tid&31)==0) sh[tid>>5] = s;
    __syncthreads();
    s = sh[0];
    #pragma unroll
    for (int w=1;w<8;w++) s += sh[w];
    float inv = 1.f/s;

    for (int j=tid; j<len; j+=256) row[j] = expf(row[j]-m)*inv;
    int pad = ((i>>7)+1)<<7;
    for (int j=len+tid; j<pad; j+=256) row[j] = 0.f;
}

// out[z*S + s] = dot(Sig[b,s,hD:hD+D], zvec[h*D:...])
__global__ void rowdot_kernel(const float* __restrict__ Sig, const float* __restrict__ zvec,
                              float* __restrict__ out)
{
    int w = threadIdx.x >> 5, lane = threadIdx.x & 31;
    int r = blockIdx.x*8 + w;
    int z = r / S_, s = r % S_;
    int b = z / H_, h = z % H_;
    const float* p  = Sig + (long)(b*S_+s)*E_ + h*D_;
    const float* zp = zvec + h*D_;
    float acc = 0.f;
    #pragma unroll
    for (int d=lane; d<D_; d+=32) acc += p[d]*zp[d];
    #pragma unroll
    for (int o=16;o;o>>=1) acc += __shfl_xor_sync(0xffffffffu, acc, o);
    if (lane==0) out[r] = acc;
}

// mem_new[b,h,d,e] = mem[h,d,e] + sum_s SigK[b,h,s,d]*U[b,h,s,e]   (A^T B, K=2048)
__global__ __launch_bounds__(256) void memupd_kernel(
    const float* __restrict__ SK, const float* __restrict__ U,
    const float* __restrict__ mem, float* __restrict__ out)
{
    int z = blockIdx.z, b = z / H_, h = z % H_;
    int e0 = blockIdx.x*64, d0 = blockIdx.y*64;
    const float* A  = SK + (long)b*S_*E_ + h*D_;
    const float* Bu = U  + (long)b*S_*E_ + h*D_;
    __shared__ float As[16][68];
    __shared__ float Bs[16][68];
    int tid = threadIdx.x, tx = tid & 15, ty = tid >> 4;
    float acc[4][4];
    #pragma unroll
    for (int i=0;i<4;i++)
        #pragma unroll
        for (int j=0;j<4;j++) acc[i][j]=0.f;

    for (int k0=0; k0<S_; k0+=16) {
        int row = tid >> 4, ch = tid & 15;
        float4 va = *(const float4*)(A  + (long)(k0+row)*E_ + d0 + ch*4);
        *(float4*)&As[row][ch*4] = va;
        float4 vb = *(const float4*)(Bu + (long)(k0+row)*E_ + e0 + ch*4);
        *(float4*)&Bs[row][ch*4] = vb;
        __syncthreads();
        #pragma unroll
        for (int k=0;k<16;k++){
            float a[4], bb[4];
            #pragma unroll
            for (int i=0;i<4;i++) a[i]  = As[k][ty*4+i];
            #pragma unroll
            for (int j=0;j<4;j++) bb[j] = Bs[k][tx*4+j];
            #pragma unroll
            for (int i=0;i<4;i++)
                #pragma unroll
                for (int j=0;j<4;j++) acc[i][j] = fmaf(a[i], bb[j], acc[i][j]);
        }
        __syncthreads();
    }
    #pragma unroll
    for (int i=0;i<4;i++){
        int d = d0 + ty*4 + i;
        #pragma unroll
        for (int j=0;j<4;j++){
            int e = e0 + tx*4 + j;
            out[((long)(b*H_+h)*D_ + d)*D_ + e] = mem[((long)h*D_ + d)*D_ + e] + acc[i][j];
        }
    }
}

// z_new[b,h,d] = z[h,d] + sum_s SigK[b,h,s,d]
__global__ void znew_kernel(const float* __restrict__ SK, const float* __restrict__ zvec,
                            float* __restrict__ out)
{
    int z = blockIdx.x, b = z / H_, h = z % H_;
    int d = threadIdx.x;
    const float* p = SK + (long)b*S_*E_ + h*D_ + d;
    double acc = 0.0;
    #pragma unroll 8
    for (int s=0; s<S_; s++) acc += (double)p[(long)s*E_];
    out[z*D_ + d] = zvec[h*D_+d] + (float)acc;
}

extern "C" void kernel_launch(void* const* d_in, const int* in_sizes, int n_in,
                              void* d_out, int out_size)
{
    const float* hs    = (const float*)d_in[0];
    const float* Wq    = (const float*)d_in[1];
    const float* Wk    = (const float*)d_in[2];
    const float* Wv    = (const float*)d_in[3];
    const float* Wo    = (const float*)d_in[4];
    const float* bo    = (const float*)d_in[5];
    const float* betas = (const float*)d_in[6];
    const float* memp  = (const float*)d_in[7];
    const float* zv    = (const float*)d_in[8];
    float* out = (float*)d_out;

    float *Q,*K,*V,*SQ,*SK,*AO,*U,*P,*Zq,*Zk;
    cudaGetSymbolAddress((void**)&Q,  g_Q);
    cudaGetSymbolAddress((void**)&K,  g_K);
    cudaGetSymbolAddress((void**)&V,  g_V);
    cudaGetSymbolAddress((void**)&SQ, g_SQ);
    cudaGetSymbolAddress((void**)&SK, g_SK);
    cudaGetSymbolAddress((void**)&AO, g_AO);
    cudaGetSymbolAddress((void**)&U,  g_U);
    cudaGetSymbolAddress((void**)&P,  g_P);
    cudaGetSymbolAddress((void**)&Zq, g_Zq);
    cudaGetSymbolAddress((void**)&Zk, g_Zk);

    const long OUT_MEM = (long)B_*S_*E_;
    const long OUT_Z   = OUT_MEM + (long)B_*H_*D_*D_;
    const int  MBS = B_*S_;
    dim3 thr(256);

    // Q/K/V projections (+ fused sigma = elu+1 for Q,K)
    sgemm_nn<<<dim3(E_/BN, MBS/BM, 1), thr>>>(hs, Wq, Q, SQ, 0, 0, 0, 0,
        MBS, E_, E_, E_, E_, E_, 0,0,0,0,0,0, MODE_SIG, 0);
    sgemm_nn<<<dim3(E_/BN, MBS/BM, 1), thr>>>(hs, Wk, K, SK, 0, 0, 0, 0,
        MBS, E_, E_, E_, E_, E_, 0,0,0,0,0,0, MODE_SIG, 0);
    sgemm_nn<<<dim3(E_/BN, MBS/BM, 1), thr>>>(hs, Wv, V, 0, 0, 0, 0, 0,
        MBS, E_, E_, E_, E_, E_, 0,0,0,0,0,0, MODE_PLAIN, 0);

    // causal scores + softmax + PV
    scores_kernel<<<dim3(S_/BN, S_/BM, BH_), thr>>>(Q, K, P);
    softmax_kernel<<<dim3(S_, BH_), thr>>>(P);
    sgemm_nn<<<dim3(D_/BN, S_/BM, BH_), thr>>>(P, V, AO, 0, 0, 0, 0, 0,
        S_, D_, S_, S_, E_, E_,
        (long)H_*S_*S_, (long)S_*S_, (long)S_*E_, (long)D_, (long)S_*E_, (long)D_,
        MODE_PLAIN, 1);

    // sigma . z row dots
    rowdot_kernel<<<BH_*S_/8, thr>>>(SQ, zv, Zq);
    rowdot_kernel<<<BH_*S_/8, thr>>>(SK, zv, Zk);

    // A_mem + gate mix (in place on AO)
    sgemm_nn<<<dim3(D_/BN, S_/BM, BH_), thr>>>(SQ, memp, AO, 0, 0, Zq, AO, betas,
        S_, D_, D_, E_, D_, E_,
        (long)S_*E_, (long)D_, 0, (long)D_*D_, (long)S_*E_, (long)D_,
        MODE_AMEM, 0);

    // U = V - delta
    sgemm_nn<<<dim3(D_/BN, S_/BM, BH_), thr>>>(SK, memp, U, 0, 0, Zk, V, 0,
        S_, D_, D_, E_, D_, E_,
        (long)S_*E_, (long)D_, 0, (long)D_*D_, (long)S_*E_, (long)D_,
        MODE_DELTA, 0);

    // memory + z updates (direct to d_out)
    memupd_kernel<<<dim3(D_/64, D_/64, BH_), thr>>>(SK, U, memp, out + OUT_MEM);
    znew_kernel<<<BH_, D_>>>(SK, zv, out + OUT_Z);

    // output projection + bias (direct to d_out)
    sgemm_nn<<<dim3(E_/BN, MBS/BM, 1), thr>>>(AO, Wo, out, 0, bo, 0, 0, 0,
        MBS, E_, E_, E_, E_, E_, 0,0,0,0,0,0, MODE_BIAS, 0);
}

// round 4
// speedup vs baseline: 1.9195x; 1.9195x over previous
#include <cuda_runtime.h>
#include <cuda_bf16.h>
#include <cstdint>
#include <math.h>

#define B_ 4
#define S_ 2048
#define E_ 1024
#define H_ 4
#define D_ 256
#define BH_ 16
#define MSZ (B_*S_*E_)

typedef __nv_bfloat16 bf16;

// ================= device scratch =================
__device__ bf16 g_HSh[MSZ], g_HSl[MSZ];
__device__ bf16 g_WqTh[E_*E_], g_WqTl[E_*E_];
__device__ bf16 g_WkTh[E_*E_], g_WkTl[E_*E_];
__device__ bf16 g_WvTh[E_*E_], g_WvTl[E_*E_];
__device__ bf16 g_WoTh[E_*E_], g_WoTl[E_*E_];
__device__ bf16 g_memTh[H_*D_*D_], g_memTl[H_*D_*D_];
__device__ bf16 g_Qh[MSZ], g_Ql[MSZ], g_Kh[MSZ], g_Kl[MSZ];
__device__ bf16 g_SQh[MSZ], g_SQl[MSZ], g_SKh[MSZ], g_SKl[MSZ];
__device__ bf16 g_ABh[MSZ], g_ABl[MSZ];
__device__ bf16 g_VTh[MSZ], g_VTl[MSZ];
__device__ bf16 g_UTh[MSZ], g_UTl[MSZ];
__device__ bf16 g_SKTh[MSZ], g_SKTl[MSZ];
__device__ float g_Pf[(size_t)BH_*S_*S_];
__device__ bf16  g_Ph[(size_t)BH_*S_*S_], g_Pl[(size_t)BH_*S_*S_];
__device__ float g_Vf[MSZ], g_Uf[MSZ], g_SKf[MSZ], g_AO[MSZ];
__device__ float g_Zq[BH_*S_], g_Zk[BH_*S_];

// ================= helpers =================
__device__ __forceinline__ uint32_t smem_u32(const void* p){
    uint32_t a;
    asm("{ .reg .u64 t; cvta.to.shared.u64 t, %1; cvt.u32.u64 %0, t; }" : "=r"(a) : "l"(p));
    return a;
}
#define SWZ(o) ((o) ^ (((o) >> 3) & 0x70))

#define CP_ASYNC(daddr, gptr) \
    asm volatile("cp.async.cg.shared.global [%0], [%1], 16;" :: "r"(daddr), "l"(gptr) : "memory")
#define CP_COMMIT() asm volatile("cp.async.commit_group;" ::: "memory")
#define CP_WAIT(n)  asm volatile("cp.async.wait_group %0;" :: "n"(n) : "memory")

__device__ __forceinline__ void ldm_x4(uint32_t& r0, uint32_t& r1, uint32_t& r2, uint32_t& r3, uint32_t a){
    asm volatile("ldmatrix.sync.aligned.m8n8.x4.shared.b16 {%0,%1,%2,%3}, [%4];"
        : "=r"(r0), "=r"(r1), "=r"(r2), "=r"(r3) : "r"(a));
}
__device__ __forceinline__ void mma16816(float* c, const uint32_t* a, const uint32_t* b){
    asm volatile("mma.sync.aligned.m16n8k16.row.col.f32.bf16.bf16.f32 "
        "{%0,%1,%2,%3}, {%4,%5,%6,%7}, {%8,%9}, {%0,%1,%2,%3};"
        : "+f"(c[0]), "+f"(c[1]), "+f"(c[2]), "+f"(c[3])
        : "r"(a[0]), "r"(a[1]), "r"(a[2]), "r"(a[3]), "r"(b[0]), "r"(b[1]));
}

__device__ __forceinline__ void store_split(bf16* ph, bf16* pl, size_t i, float v){
    bf16 h = __float2bfloat16(v);
    ph[i] = h;
    pl[i] = __float2bfloat16(v - __bfloat162float(h));
}

enum { EP_F32=0, EP_SIGQK=1, EP_BIAS=2, EP_AMEM=3, EP_DELTA=4, EP_MEMUPD=5 };

#define STG_BYTES 65536      // 4 tiles (Ah,Al,Bh,Bl) x 16KB
#define SMEM_BYTES (2*STG_BYTES)

// ================= HMMA GEMM: D = A @ B^T =================
// A[M,K], B[N,K] bf16 hi/lo, K-major. 128x128 tiles, K-chunk 64, 2-stage cp.async.
__global__ void __launch_bounds__(256,1) tc_gemm(
    const bf16* __restrict__ Ahg, const bf16* __restrict__ Alg,
    const bf16* __restrict__ Bhg, const bf16* __restrict__ Blg,
    int K, int lda, int ldb, int ldc,
    long sAb, long sAh, long sBb, long sBh, long sCb, long sCh,
    int mode, int causal,
    float* __restrict__ C, bf16* __restrict__ O1h, bf16* __restrict__ O1l,
    bf16* __restrict__ O2h, bf16* __restrict__ O2l,
    const float* __restrict__ rowdiv, const float* __restrict__ mix,
    const float* __restrict__ betas, const float* __restrict__ bias)
{
    extern __shared__ char smemc[];
    int z = blockIdx.z, bb = z / H_, hh = z % H_;
    int m0 = blockIdx.y*128, n0 = blockIdx.x*128;
    if (causal==1 && n0 > m0) return;
    int Keff = (causal==2) ? min(K, m0+128) : K;

    const bf16* Ah = Ahg + (size_t)bb*sAb + (size_t)hh*sAh;
    const bf16* Al = Alg + (size_t)bb*sAb + (size_t)hh*sAh;
    const bf16* Bh = Bhg + (size_t)bb*sBb + (size_t)hh*sBh;
    const bf16* Bl = Blg + (size_t)bb*sBb + (size_t)hh*sBh;
    size_t coff = (size_t)bb*sCb + (size_t)hh*sCh;

    int tid = threadIdx.x, wid = tid >> 5, lid = tid & 31;
    uint32_t sb = smem_u32(smemc);
    int wm = wid & 1, wn = wid >> 1;         // 2 x 4 warp grid
    int mbase = wm*64, nbase = wn*32;

    float acc[4][4][4];
    #pragma unroll
    for (int i=0;i<4;i++)
        #pragma unroll
        for (int j=0;j<4;j++)
            #pragma unroll
            for (int r=0;r<4;r++) acc[i][j][r]=0.f;

    int nch = Keff >> 6;
    int row_l = tid >> 3, v_l = tid & 7;     // loader: 32 rows/pass, 8 x 16B cols

    // ---- issue loads for chunk ci into stage s ----
    auto issue = [&](int ci, int s){
        int stg = s*STG_BYTES, kc0 = ci << 6;
        const bf16* ptrs[4] = {Ah, Al, Bh, Bl};
        int rb[4] = {m0, m0, n0, n0};
        int lds[4] = {lda, lda, ldb, ldb};
        #pragma unroll
        for (int bfi=0; bfi<4; bfi++){
            #pragma unroll
            for (int i=0;i<4;i++){
                int row = row_l + 32*i;
                uint32_t da = sb + stg + bfi*16384 + SWZ(row*128 + v_l*16);
                const void* gp = ptrs[bfi] + (size_t)(rb[bfi]+row)*lds[bfi] + kc0 + v_l*8;
                CP_ASYNC(da, gp);
            }
        }
        CP_COMMIT();
    };

    issue(0, 0);
    if (nch > 1) issue(1, 1);

    for (int ci=0; ci<nch; ci++){
        if (ci+1 < nch) { CP_WAIT(1); } else { CP_WAIT(0); }
        __syncthreads();
        int stg = (ci&1)*STG_BYTES;

        #pragma unroll
        for (int ks=0; ks<4; ks++){
            int colb = ks*32 + ((lid>>4)&1)*16;
            uint32_t ah[4][4], al[4][4];
            #pragma unroll
            for (int mt=0; mt<4; mt++){
                int row = mbase + mt*16 + (lid & 15);
                uint32_t off = SWZ(row*128 + colb);
                ldm_x4(ah[mt][0],ah[mt][1],ah[mt][2],ah[mt][3], sb+stg+off);
                ldm_x4(al[mt][0],al[mt][1],al[mt][2],al[mt][3], sb+stg+16384+off);
            }
            uint32_t bh[4][2], bl[4][2];
            #pragma unroll
            for (int g=0; g<2; g++){
                int row = nbase + g*16 + (lid & 7) + ((lid>>4)&1)*8;
                int cb2 = ks*32 + ((lid>>3)&1)*16;
                uint32_t off = SWZ(row*128 + cb2);
                uint32_t r0,r1,r2,r3;
                ldm_x4(r0,r1,r2,r3, sb+stg+32768+off);
                bh[2*g][0]=r0; bh[2*g][1]=r1; bh[2*g+1][0]=r2; bh[2*g+1][1]=r3;
                ldm_x4(r0,r1,r2,r3, sb+stg+49152+off);
                bl[2*g][0]=r0; bl[2*g][1]=r1; bl[2*g+1][0]=r2; bl[2*g+1][1]=r3;
            }
            #pragma unroll
            for (int mt=0; mt<4; mt++)
                #pragma unroll
                for (int nt=0; nt<4; nt++){
                    mma16816(acc[mt][nt], ah[mt], bh[nt]);
                    mma16816(acc[mt][nt], ah[mt], bl[nt]);
                    mma16816(acc[mt][nt], al[mt], bh[nt]);
                }
        }
        __syncthreads();
        if (ci+2 < nch) issue(ci+2, ci&1);
    }

    // ---- epilogue: stage through smem, coalesced modal stores ----
    float* buf = (float*)smemc;              // 128 x 132 floats = 67.5KB
    int tg = lid >> 2, t4 = lid & 3;
    #pragma unroll
    for (int mt=0; mt<4; mt++)
        #pragma unroll
        for (int nt=0; nt<4; nt++)
            #pragma unroll
            for (int r=0; r<4; r++){
                int m = mbase + mt*16 + tg + (r>=2 ? 8 : 0);
                int c = nbase + nt*8 + t4*2 + (r&1);
                buf[m*132 + c] = acc[mt][nt][r];
            }
    __syncthreads();

    float gate = 0.f;
    if (mode == EP_AMEM) gate = 1.f/(1.f + expf(-betas[hh]));

    #pragma unroll 4
    for (int e=0; e<64; e++){
        int flat = e*256 + tid;
        int row = flat >> 7, col = flat & 127;
        float v = buf[row*132 + col];
        int m = m0 + row, c = n0 + col;
        size_t idx = coff + (size_t)m*ldc + c;
        if (mode == EP_F32) {
            C[idx] = v;
        } else if (mode == EP_SIGQK) {
            store_split(O1h, O1l, idx, v);
            float sg = v > 0.f ? v + 1.f : expf(v);
            store_split(O2h, O2l, idx, sg);
            if (C) C[idx] = sg;
        } else if (mode == EP_BIAS) {
            C[idx] = v + bias[c];
        } else if (mode == EP_AMEM) {
            float rinv = 1.f/(rowdiv[(size_t)z*S_ + m] + 1e-6f);
            float val = gate*(v*rinv) + (1.f-gate)*mix[idx];
            store_split(O1h, O1l, idx, val);
        } else if (mode == EP_DELTA) {
            float rinv = 1.f/(rowdiv[(size_t)z*S_ + m] + 1e-6f);
            C[idx] = mix[idx] - v*rinv;
        } else { // EP_MEMUPD
            float mv = mix[(size_t)hh*D_*D_ + (size_t)m*D_ + c];
            C[idx] = mv + v;
        }
    }
}

// ================= small kernels =================
__global__ void split_f32(const float* __restrict__ src, bf16* __restrict__ h, bf16* __restrict__ l, int n4){
    int i = blockIdx.x*blockDim.x + threadIdx.x;
    if (i >= n4) return;
    float4 v = ((const float4*)src)[i];
    size_t o = (size_t)i*4;
    store_split(h, l, o+0, v.x); store_split(h, l, o+1, v.y);
    store_split(h, l, o+2, v.z); store_split(h, l, o+3, v.w);
}

__global__ void transW(const float* __restrict__ W, bf16* __restrict__ Th, bf16* __restrict__ Tl){
    __shared__ float t[32][33];
    int k0 = blockIdx.x*32, n0 = blockIdx.y*32;
    int tx = threadIdx.x, ty = threadIdx.y;
    #pragma unroll
    for (int i=0;i<32;i+=8) t[ty+i][tx] = W[(size_t)(k0+ty+i)*E_ + n0+tx];
    __syncthreads();
    #pragma unroll
    for (int i=0;i<32;i+=8){
        size_t o = (size_t)(n0+ty+i)*E_ + k0+tx;
        store_split(Th, Tl, o, t[tx][ty+i]);
    }
}

__global__ void transBH(const float* __restrict__ X, bf16* __restrict__ Th, bf16* __restrict__ Tl){
    __shared__ float t[32][33];
    int z = blockIdx.z, b = z / H_, h = z % H_;
    int s0 = blockIdx.x*32, d0 = blockIdx.y*32;
    int tx = threadIdx.x, ty = threadIdx.y;
    const float* src = X + (size_t)b*S_*E_ + h*D_;
    #pragma unroll
    for (int i=0;i<32;i+=8) t[ty+i][tx] = src[(size_t)(s0+ty+i)*E_ + d0+tx];
    __syncthreads();
    #pragma unroll
    for (int i=0;i<32;i+=8){
        size_t o = (size_t)z*D_*S_ + (size_t)(d0+ty+i)*S_ + s0+tx;
        store_split(Th, Tl, o, t[tx][ty+i]);
    }
}

__global__ void transMem(const float* __restrict__ M, bf16* __restrict__ Th, bf16* __restrict__ Tl){
    __shared__ float t[32][33];
    int h = blockIdx.z;
    int d0 = blockIdx.x*32, e0 = blockIdx.y*32;
    int tx = threadIdx.x, ty = threadIdx.y;
    #pragma unroll
    for (int i=0;i<32;i+=8) t[ty+i][tx] = M[(size_t)h*D_*D_ + (size_t)(d0+ty+i)*D_ + e0+tx];
    __syncthreads();
    #pragma unroll
    for (int i=0;i<32;i+=8){
        size_t o = (size_t)h*D_*D_ + (size_t)(e0+ty+i)*D_ + d0+tx;
        store_split(Th, Tl, o, t[tx][ty+i]);
    }
}

__global__ void softmax_split(const float* __restrict__ P, bf16* __restrict__ Ph, bf16* __restrict__ Pl){
    int i = blockIdx.x, z = blockIdx.y, tid = threadIdx.x;
    const float* row = P + ((size_t)z*S_ + i)*S_;
    size_t orow = ((size_t)z*S_ + i)*S_;
    int len = i + 1;
    __shared__ float sh[8];

    float m = -3.4e38f;
    for (int j=tid; j<len; j+=256) m = fmaxf(m, row[j]);
    #pragma unroll
    for (int o=16;o;o>>=1) m = fmaxf(m, __shfl_xor_sync(0xffffffffu, m, o));
    if ((tid&31)==0) sh[tid>>5] = m;
    __syncthreads();
    m = sh[0];
    #pragma unroll
    for (int w=1;w<8;w++) m = fmaxf(m, sh[w]);
    __syncthreads();

    float s = 0.f;
    for (int j=tid; j<len; j+=256) s += expf(row[j]-m);
    #pragma unroll
    for (int o=16;o;o>>=1) s += __shfl_xor_sync(0xffffffffu, s, o);
    if ((tid&31)==0) sh[tid>>5] = s;
    __syncthreads();
    s = sh[0];
    #pragma unroll
    for (int w=1;w<8;w++) s += sh[w];
    float inv = 1.f/s;

    for (int j=tid; j<len; j+=256) store_split(Ph, Pl, orow+j, expf(row[j]-m)*inv);
    int pad = ((i>>7)+1)<<7;
    for (int j=len+tid; j<pad; j+=256){ Ph[orow+j]=__float2bfloat16(0.f); Pl[orow+j]=__float2bfloat16(0.f); }
}

__global__ void rowdot_split(const bf16* __restrict__ Hh, const bf16* __restrict__ Hl,
                             const float* __restrict__ zvec, float* __restrict__ out){
    int w = threadIdx.x >> 5, lane = threadIdx.x & 31;
    int r = blockIdx.x*8 + w;
    int z = r / S_, s = r % S_;
    int b = z / H_, h = z % H_;
    size_t base = (size_t)(b*S_+s)*E_ + h*D_;
    const float* zp = zvec + h*D_;
    float acc = 0.f;
    #pragma unroll
    for (int d=lane; d<D_; d+=32)
        acc += (__bfloat162float(Hh[base+d]) + __bfloat162float(Hl[base+d])) * zp[d];
    #pragma unroll
    for (int o=16;o;o>>=1) acc += __shfl_xor_sync(0xffffffffu, acc, o);
    if (lane==0) out[r] = acc;
}

__global__ void znew_kernel(const float* __restrict__ SK, const float* __restrict__ zvec,
                            float* __restrict__ out){
    int z = blockIdx.x, b = z / H_, h = z % H_;
    int d = threadIdx.x;
    const float* p = SK + (size_t)b*S_*E_ + h*D_ + d;
    double acc = 0.0;
    #pragma unroll 8
    for (int s=0; s<S_; s++) acc += (double)p[(size_t)s*E_];
    out[z*D_ + d] = zvec[h*D_+d] + (float)acc;
}

// ================= launch =================
extern "C" void kernel_launch(void* const* d_in, const int* in_sizes, int n_in,
                              void* d_out, int out_size)
{
    const float* hs    = (const float*)d_in[0];
    const float* Wq    = (const float*)d_in[1];
    const float* Wk    = (const float*)d_in[2];
    const float* Wv    = (const float*)d_in[3];
    const float* Wo    = (const float*)d_in[4];
    const float* bo    = (const float*)d_in[5];
    const float* betas = (const float*)d_in[6];
    const float* memp  = (const float*)d_in[7];
    const float* zv    = (const float*)d_in[8];
    float* out = (float*)d_out;

    cudaFuncSetAttribute(tc_gemm, cudaFuncAttributeMaxDynamicSharedMemorySize, SMEM_BYTES);

#define GS(var, sym) cudaGetSymbolAddress((void**)&var, sym)
    bf16 *HSh,*HSl,*WqTh,*WqTl,*WkTh,*WkTl,*WvTh,*WvTl,*WoTh,*WoTl,*memTh,*memTl;
    bf16 *Qh,*Ql,*Kh,*Kl,*SQh,*SQl,*SKh,*SKl,*ABh,*ABl,*VTh,*VTl,*UTh,*UTl,*SKTh,*SKTl,*Ph,*Pl;
    float *Pf,*Vf,*Uf,*SKf,*AO,*Zq,*Zk;
    GS(HSh,g_HSh); GS(HSl,g_HSl);
    GS(WqTh,g_WqTh); GS(WqTl,g_WqTl); GS(WkTh,g_WkTh); GS(WkTl,g_WkTl);
    GS(WvTh,g_WvTh); GS(WvTl,g_WvTl); GS(WoTh,g_WoTh); GS(WoTl,g_WoTl);
    GS(memTh,g_memTh); GS(memTl,g_memTl);
    GS(Qh,g_Qh); GS(Ql,g_Ql); GS(Kh,g_Kh); GS(Kl,g_Kl);
    GS(SQh,g_SQh); GS(SQl,g_SQl); GS(SKh,g_SKh); GS(SKl,g_SKl);
    GS(ABh,g_ABh); GS(ABl,g_ABl);
    GS(VTh,g_VTh); GS(VTl,g_VTl); GS(UTh,g_UTh); GS(UTl,g_UTl);
    GS(SKTh,g_SKTh); GS(SKTl,g_SKTl);
    GS(Ph,g_Ph); GS(Pl,g_Pl); GS(Pf,g_Pf);
    GS(Vf,g_Vf); GS(Uf,g_Uf); GS(SKf,g_SKf); GS(AO,g_AO);
    GS(Zq,g_Zq); GS(Zk,g_Zk);

    const long OUT_MEM = (long)B_*S_*E_;
    const long OUT_Z   = OUT_MEM + (long)B_*H_*D_*D_;
    dim3 t256(256), t328(32,8);

    // input conversions
    split_f32<<<MSZ/1024, t256>>>(hs, HSh, HSl, MSZ/4);
    transW<<<dim3(32,32), t328>>>(Wq, WqTh, WqTl);
    transW<<<dim3(32,32), t328>>>(Wk, WkTh, WkTl);
    transW<<<dim3(32,32), t328>>>(Wv, WvTh, WvTl);
    transW<<<dim3(32,32), t328>>>(Wo, WoTh, WoTl);
    transMem<<<dim3(8,8,H_), t328>>>(memp, memTh, memTl);

    // projections
    tc_gemm<<<dim3(8,64,1), t256, SMEM_BYTES>>>(HSh,HSl,WqTh,WqTl, E_,E_,E_,E_,
        0,0,0,0,0,0, EP_SIGQK,0, 0, Qh,Ql, SQh,SQl, 0,0,0,0);
    tc_gemm<<<dim3(8,64,1), t256, SMEM_BYTES>>>(HSh,HSl,WkTh,WkTl, E_,E_,E_,E_,
        0,0,0,0,0,0, EP_SIGQK,0, SKf, Kh,Kl, SKh,SKl, 0,0,0,0);
    tc_gemm<<<dim3(8,64,1), t256, SMEM_BYTES>>>(HSh,HSl,WvTh,WvTl, E_,E_,E_,E_,
        0,0,0,0,0,0, EP_F32,0, Vf, 0,0,0,0, 0,0,0,0);

    transBH<<<dim3(64,8,BH_), t328>>>(Vf, VTh, VTl);

    // scores (causal tile-skip) -> softmax(split) -> PV (K clamp)
    tc_gemm<<<dim3(16,16,BH_), t256, SMEM_BYTES>>>(Qh,Ql,Kh,Kl, D_, E_,E_,S_,
        (long)S_*E_, D_, (long)S_*E_, D_, (long)H_*S_*S_, (long)S_*S_,
        EP_F32,1, Pf, 0,0,0,0, 0,0,0,0);
    softmax_split<<<dim3(S_,BH_), t256>>>(Pf, Ph, Pl);
    tc_gemm<<<dim3(2,16,BH_), t256, SMEM_BYTES>>>(Ph,Pl,VTh,VTl, S_, S_,S_,E_,
        (long)H_*S_*S_, (long)S_*S_, (long)H_*D_*S_, (long)D_*S_, (long)S_*E_, (long)D_,
        EP_F32,2, AO, 0,0,0,0, 0,0,0,0);

    // sigma . z
    rowdot_split<<<BH_*S_/8, t256>>>(SQh, SQl, zv, Zq);
    rowdot_split<<<BH_*S_/8, t256>>>(SKh, SKl, zv, Zk);

    // A_mem + gate mix -> split AB
    tc_gemm<<<dim3(2,16,BH_), t256, SMEM_BYTES>>>(SQh,SQl,memTh,memTl, D_, E_,D_,E_,
        (long)S_*E_, D_, 0, (long)D_*D_, (long)S_*E_, (long)D_,
        EP_AMEM,0, 0, ABh,ABl, 0,0, Zq, AO, betas, 0);

    // U = V - delta
    tc_gemm<<<dim3(2,16,BH_), t256, SMEM_BYTES>>>(SKh,SKl,memTh,memTl, D_, E_,D_,E_,
        (long)S_*E_, D_, 0, (long)D_*D_, (long)S_*E_, (long)D_,
        EP_DELTA,0, Uf, 0,0,0,0, Zk, Vf, 0, 0);

    transBH<<<dim3(64,8,BH_), t328>>>(Uf, UTh, UTl);
    transBH<<<dim3(64,8,BH_), t328>>>(SKf, SKTh, SKTl);

    // mem_new = mem + SK^T @ U  (direct to d_out)
    tc_gemm<<<dim3(2,2,BH_), t256, SMEM_BYTES>>>(SKTh,SKTl,UTh,UTl, S_, S_,S_,D_,
        (long)H_*D_*S_, (long)D_*S_, (long)H_*D_*S_, (long)D_*S_, (long)H_*D_*D_, (long)D_*D_,
        EP_MEMUPD,0, out+OUT_MEM, 0,0,0,0, 0, memp, 0, 0);

    znew_kernel<<<BH_, D_>>>(SKf, zv, out+OUT_Z);

    // out projection + bias
    tc_gemm<<<dim3(8,64,1), t256, SMEM_BYTES>>>(ABh,ABl,WoTh,WoTl, E_,E_,E_,E_,
        0,0,0,0,0,0, EP_BIAS,0, out, 0,0,0,0, 0,0,0, bo);
}

// round 5
// speedup vs baseline: 2.2791x; 1.1873x over previous
#include <cuda_runtime.h>
#include <cuda_bf16.h>
#include <cstdint>
#include <math.h>

#define B_ 4
#define S_ 2048
#define E_ 1024
#define H_ 4
#define D_ 256
#define BH_ 16
#define MSZ (B_*S_*E_)

typedef __nv_bfloat16 bf16;

// ================= device scratch =================
__device__ bf16 g_HSh[MSZ], g_HSl[MSZ];
__device__ bf16 g_WqTh[E_*E_], g_WqTl[E_*E_];
__device__ bf16 g_WkTh[E_*E_], g_WkTl[E_*E_];
__device__ bf16 g_WvTh[E_*E_], g_WvTl[E_*E_];
__device__ bf16 g_WoTh[E_*E_], g_WoTl[E_*E_];
__device__ bf16 g_memTh[H_*D_*D_], g_memTl[H_*D_*D_];
__device__ bf16 g_Qh[MSZ], g_Ql[MSZ], g_Kh[MSZ], g_Kl[MSZ];
__device__ bf16 g_SQh[MSZ], g_SQl[MSZ], g_SKh[MSZ], g_SKl[MSZ];
__device__ bf16 g_ABh[MSZ], g_ABl[MSZ];
__device__ bf16 g_VTh[MSZ], g_VTl[MSZ];
__device__ bf16 g_UTh[MSZ], g_UTl[MSZ];
__device__ bf16 g_SKTh[MSZ], g_SKTl[MSZ];
__device__ float g_Pf[(size_t)BH_*S_*S_];
__device__ bf16  g_Ph[(size_t)BH_*S_*S_], g_Pl[(size_t)BH_*S_*S_];
__device__ float g_Vf[MSZ], g_Uf[MSZ], g_SKf[MSZ], g_AO[MSZ];
__device__ float g_Zq[BH_*S_], g_Zk[BH_*S_];
__device__ float g_Zpart[BH_*8*D_];

// ================= helpers =================
__device__ __forceinline__ uint32_t smem_u32(const void* p){
    uint32_t a;
    asm("{ .reg .u64 t; cvta.to.shared.u64 t, %1; cvt.u32.u64 %0, t; }" : "=r"(a) : "l"(p));
    return a;
}
#define SWZ(o) ((o) ^ (((o) >> 3) & 0x70))

#define CP_ASYNC(daddr, gptr) \
    asm volatile("cp.async.cg.shared.global [%0], [%1], 16;" :: "r"(daddr), "l"(gptr) : "memory")
#define CP_COMMIT() asm volatile("cp.async.commit_group;" ::: "memory")
#define CP_WAIT(n)  asm volatile("cp.async.wait_group %0;" :: "n"(n) : "memory")

__device__ __forceinline__ void ldm_x4(uint32_t& r0, uint32_t& r1, uint32_t& r2, uint32_t& r3, uint32_t a){
    asm volatile("ldmatrix.sync.aligned.m8n8.x4.shared.b16 {%0,%1,%2,%3}, [%4];"
        : "=r"(r0), "=r"(r1), "=r"(r2), "=r"(r3) : "r"(a));
}
__device__ __forceinline__ void mma16816(float* c, const uint32_t* a, const uint32_t* b){
    asm volatile("mma.sync.aligned.m16n8k16.row.col.f32.bf16.bf16.f32 "
        "{%0,%1,%2,%3}, {%4,%5,%6,%7}, {%8,%9}, {%0,%1,%2,%3};"
        : "+f"(c[0]), "+f"(c[1]), "+f"(c[2]), "+f"(c[3])
        : "r"(a[0]), "r"(a[1]), "r"(a[2]), "r"(a[3]), "r"(b[0]), "r"(b[1]));
}

__device__ __forceinline__ void store_split(bf16* ph, bf16* pl, size_t i, float v){
    bf16 h = __float2bfloat16(v);
    ph[i] = h;
    pl[i] = __float2bfloat16(v - __bfloat162float(h));
}

enum { EP_F32=0, EP_SIGQK=1, EP_BIAS=2, EP_AMEM=3, EP_DELTA=4, EP_MEMUPD=5 };

#define STG_BYTES 65536      // 4 tiles (Ah,Al,Bh,Bl) x 16KB
#define SMEM_BYTES (2*STG_BYTES)

// ================= HMMA GEMM: D = A @ B^T =================
// A[M,K], B[N,K] bf16 hi/lo, K-major. 128x128 tiles, K-chunk 64, 2-stage cp.async.
__global__ void __launch_bounds__(256,1) tc_gemm(
    const bf16* __restrict__ Ahg, const bf16* __restrict__ Alg,
    const bf16* __restrict__ Bhg, const bf16* __restrict__ Blg,
    int K, int lda, int ldb, int ldc,
    long sAb, long sAh, long sBb, long sBh, long sCb, long sCh,
    int mode, int causal,
    float* __restrict__ C, bf16* __restrict__ O1h, bf16* __restrict__ O1l,
    bf16* __restrict__ O2h, bf16* __restrict__ O2l,
    const float* __restrict__ rowdiv, const float* __restrict__ mix,
    const float* __restrict__ betas, const float* __restrict__ bias)
{
    extern __shared__ char smemc[];
    int z = blockIdx.z, bb = z / H_, hh = z % H_;
    int m0 = blockIdx.y*128, n0 = blockIdx.x*128;
    if (causal==1 && n0 > m0) return;
    int Keff = (causal==2) ? min(K, m0+128) : K;

    const bf16* Ah = Ahg + (size_t)bb*sAb + (size_t)hh*sAh;
    const bf16* Al = Alg + (size_t)bb*sAb + (size_t)hh*sAh;
    const bf16* Bh = Bhg + (size_t)bb*sBb + (size_t)hh*sBh;
    const bf16* Bl = Blg + (size_t)bb*sBb + (size_t)hh*sBh;
    size_t coff = (size_t)bb*sCb + (size_t)hh*sCh;

    int tid = threadIdx.x, wid = tid >> 5, lid = tid & 31;
    uint32_t sb = smem_u32(smemc);
    int wm = wid & 1, wn = wid >> 1;         // 2 x 4 warp grid
    int mbase = wm*64, nbase = wn*32;

    float acc[4][4][4];
    #pragma unroll
    for (int i=0;i<4;i++)
        #pragma unroll
        for (int j=0;j<4;j++)
            #pragma unroll
            for (int r=0;r<4;r++) acc[i][j][r]=0.f;

    int nch = Keff >> 6;
    int row_l = tid >> 3, v_l = tid & 7;     // loader: 32 rows/pass, 8 x 16B cols

    // ---- issue loads for chunk ci into stage s ----
    auto issue = [&](int ci, int s){
        int stg = s*STG_BYTES, kc0 = ci << 6;
        const bf16* ptrs[4] = {Ah, Al, Bh, Bl};
        int rb[4] = {m0, m0, n0, n0};
        int lds[4] = {lda, lda, ldb, ldb};
        #pragma unroll
        for (int bfi=0; bfi<4; bfi++){
            #pragma unroll
            for (int i=0;i<4;i++){
                int row = row_l + 32*i;
                uint32_t da = sb + stg + bfi*16384 + SWZ(row*128 + v_l*16);
                const void* gp = ptrs[bfi] + (size_t)(rb[bfi]+row)*lds[bfi] + kc0 + v_l*8;
                CP_ASYNC(da, gp);
            }
        }
        CP_COMMIT();
    };

    issue(0, 0);
    if (nch > 1) issue(1, 1);

    for (int ci=0; ci<nch; ci++){
        if (ci+1 < nch) { CP_WAIT(1); } else { CP_WAIT(0); }
        __syncthreads();
        int stg = (ci&1)*STG_BYTES;

        #pragma unroll
        for (int ks=0; ks<4; ks++){
            int colb = ks*32 + ((lid>>4)&1)*16;
            uint32_t ah[4][4], al[4][4];
            #pragma unroll
            for (int mt=0; mt<4; mt++){
                int row = mbase + mt*16 + (lid & 15);
                uint32_t off = SWZ(row*128 + colb);
                ldm_x4(ah[mt][0],ah[mt][1],ah[mt][2],ah[mt][3], sb+stg+off);
                ldm_x4(al[mt][0],al[mt][1],al[mt][2],al[mt][3], sb+stg+16384+off);
            }
            uint32_t bh[4][2], bl[4][2];
            #pragma unroll
            for (int g=0; g<2; g++){
                int row = nbase + g*16 + (lid & 7) + ((lid>>4)&1)*8;
                int cb2 = ks*32 + ((lid>>3)&1)*16;
                uint32_t off = SWZ(row*128 + cb2);
                uint32_t r0,r1,r2,r3;
                ldm_x4(r0,r1,r2,r3, sb+stg+32768+off);
                bh[2*g][0]=r0; bh[2*g][1]=r1; bh[2*g+1][0]=r2; bh[2*g+1][1]=r3;
                ldm_x4(r0,r1,r2,r3, sb+stg+49152+off);
                bl[2*g][0]=r0; bl[2*g][1]=r1; bl[2*g+1][0]=r2; bl[2*g+1][1]=r3;
            }
            #pragma unroll
            for (int mt=0; mt<4; mt++)
                #pragma unroll
                for (int nt=0; nt<4; nt++){
                    mma16816(acc[mt][nt], ah[mt], bh[nt]);
                    mma16816(acc[mt][nt], ah[mt], bl[nt]);
                    mma16816(acc[mt][nt], al[mt], bh[nt]);
                }
        }
        __syncthreads();
        if (ci+2 < nch) issue(ci+2, ci&1);
    }

    // ---- epilogue: stage through smem, coalesced modal stores ----
    float* buf = (float*)smemc;              // 128 x 132 floats = 67.5KB
    int tg = lid >> 2, t4 = lid & 3;
    #pragma unroll
    for (int mt=0; mt<4; mt++)
        #pragma unroll
        for (int nt=0; nt<4; nt++)
            #pragma unroll
            for (int r=0; r<4; r++){
                int m = mbase + mt*16 + tg + (r>=2 ? 8 : 0);
                int c = nbase + nt*8 + t4*2 + (r&1);
                buf[m*132 + c] = acc[mt][nt][r];
            }
    __syncthreads();

    float gate = 0.f;
    if (mode == EP_AMEM) gate = 1.f/(1.f + __expf(-betas[hh]));

    #pragma unroll 4
    for (int e=0; e<64; e++){
        int flat = e*256 + tid;
        int row = flat >> 7, col = flat & 127;
        float v = buf[row*132 + col];
        int m = m0 + row, c = n0 + col;
        size_t idx = coff + (size_t)m*ldc + c;
        if (mode == EP_F32) {
            C[idx] = v;
        } else if (mode == EP_SIGQK) {
            store_split(O1h, O1l, idx, v);
            float sg = v > 0.f ? v + 1.f : __expf(v);
            store_split(O2h, O2l, idx, sg);
            if (C) C[idx] = sg;
        } else if (mode == EP_BIAS) {
            C[idx] = v + bias[c];
        } else if (mode == EP_AMEM) {
            float rinv = 1.f/(rowdiv[(size_t)z*S_ + m] + 1e-6f);
            float val = gate*(v*rinv) + (1.f-gate)*mix[idx];
            store_split(O1h, O1l, idx, val);
        } else if (mode == EP_DELTA) {
            float rinv = 1.f/(rowdiv[(size_t)z*S_ + m] + 1e-6f);
            C[idx] = mix[idx] - v*rinv;
        } else { // EP_MEMUPD
            float mv = mix[(size_t)hh*D_*D_ + (size_t)m*D_ + c];
            C[idx] = mv + v;
        }
    }
}

// ================= small kernels =================
__global__ void split_f32(const float* __restrict__ src, bf16* __restrict__ h, bf16* __restrict__ l, int n4){
    int i = blockIdx.x*blockDim.x + threadIdx.x;
    if (i >= n4) return;
    float4 v = ((const float4*)src)[i];
    size_t o = (size_t)i*4;
    store_split(h, l, o+0, v.x); store_split(h, l, o+1, v.y);
    store_split(h, l, o+2, v.z); store_split(h, l, o+3, v.w);
}

__global__ void transW(const float* __restrict__ W, bf16* __restrict__ Th, bf16* __restrict__ Tl){
    __shared__ float t[32][33];
    int k0 = blockIdx.x*32, n0 = blockIdx.y*32;
    int tx = threadIdx.x, ty = threadIdx.y;
    #pragma unroll
    for (int i=0;i<32;i+=8) t[ty+i][tx] = W[(size_t)(k0+ty+i)*E_ + n0+tx];
    __syncthreads();
    #pragma unroll
    for (int i=0;i<32;i+=8){
        size_t o = (size_t)(n0+ty+i)*E_ + k0+tx;
        store_split(Th, Tl, o, t[tx][ty+i]);
    }
}

__global__ void transBH(const float* __restrict__ X, bf16* __restrict__ Th, bf16* __restrict__ Tl){
    __shared__ float t[32][33];
    int z = blockIdx.z, b = z / H_, h = z % H_;
    int s0 = blockIdx.x*32, d0 = blockIdx.y*32;
    int tx = threadIdx.x, ty = threadIdx.y;
    const float* src = X + (size_t)b*S_*E_ + h*D_;
    #pragma unroll
    for (int i=0;i<32;i+=8) t[ty+i][tx] = src[(size_t)(s0+ty+i)*E_ + d0+tx];
    __syncthreads();
    #pragma unroll
    for (int i=0;i<32;i+=8){
        size_t o = (size_t)z*D_*S_ + (size_t)(d0+ty+i)*S_ + s0+tx;
        store_split(Th, Tl, o, t[tx][ty+i]);
    }
}

__global__ void transMem(const float* __restrict__ M, bf16* __restrict__ Th, bf16* __restrict__ Tl){
    __shared__ float t[32][33];
    int h = blockIdx.z;
    int d0 = blockIdx.x*32, e0 = blockIdx.y*32;
    int tx = threadIdx.x, ty = threadIdx.y;
    #pragma unroll
    for (int i=0;i<32;i+=8) t[ty+i][tx] = M[(size_t)h*D_*D_ + (size_t)(d0+ty+i)*D_ + e0+tx];
    __syncthreads();
    #pragma unroll
    for (int i=0;i<32;i+=8){
        size_t o = (size_t)h*D_*D_ + (size_t)(e0+ty+i)*D_ + d0+tx;
        store_split(Th, Tl, o, t[tx][ty+i]);
    }
}

// single-pass causal softmax: row cached in registers, one __expf per element,
// fused normalize + bf16 hi/lo split store, zero-pad to 128 boundary.
__global__ void __launch_bounds__(256) softmax_split(
    const float* __restrict__ P, bf16* __restrict__ Ph, bf16* __restrict__ Pl)
{
    int i = blockIdx.x, z = blockIdx.y, tid = threadIdx.x;
    const float* row = P + ((size_t)z*S_ + i)*S_;
    size_t orow = ((size_t)z*S_ + i)*S_;
    int len = i + 1;
    int pad = ((i>>7)+1)<<7;
    __shared__ float sh[8];

    float v[8];
    float m = -3.4e38f;
    #pragma unroll
    for (int c=0;c<8;c++){
        int j = tid + (c<<8);
        if (j < len) { v[c] = row[j]; m = fmaxf(m, v[c]); }
        else v[c] = -3.4e38f;
    }
    #pragma unroll
    for (int o=16;o;o>>=1) m = fmaxf(m, __shfl_xor_sync(0xffffffffu, m, o));
    if ((tid&31)==0) sh[tid>>5] = m;
    __syncthreads();
    m = sh[0];
    #pragma unroll
    for (int w=1;w<8;w++) m = fmaxf(m, sh[w]);
    __syncthreads();

    float s = 0.f;
    #pragma unroll
    for (int c=0;c<8;c++){
        int j = tid + (c<<8);
        if (j < len) { v[c] = __expf(v[c]-m); s += v[c]; }
    }
    #pragma unroll
    for (int o=16;o;o>>=1) s += __shfl_xor_sync(0xffffffffu, s, o);
    if ((tid&31)==0) sh[tid>>5] = s;
    __syncthreads();
    s = sh[0];
    #pragma unroll
    for (int w=1;w<8;w++) s += sh[w];
    float inv = 1.f/s;

    #pragma unroll
    for (int c=0;c<8;c++){
        int j = tid + (c<<8);
        if (j < pad){
            float p = (j < len) ? v[c]*inv : 0.f;
            store_split(Ph, Pl, orow + j, p);
        }
    }
}

__global__ void rowdot_split(const bf16* __restrict__ Hh, const bf16* __restrict__ Hl,
                             const float* __restrict__ zvec, float* __restrict__ out){
    int w = threadIdx.x >> 5, lane = threadIdx.x & 31;
    int r = blockIdx.x*8 + w;
    int z = r / S_, s = r % S_;
    int b = z / H_, h = z % H_;
    size_t base = (size_t)(b*S_+s)*E_ + h*D_;
    const float* zp = zvec + h*D_;
    float acc = 0.f;
    #pragma unroll
    for (int d=lane; d<D_; d+=32)
        acc += (__bfloat162float(Hh[base+d]) + __bfloat162float(Hl[base+d])) * zp[d];
    #pragma unroll
    for (int o=16;o;o>>=1) acc += __shfl_xor_sync(0xffffffffu, acc, o);
    if (lane==0) out[r] = acc;
}

// z_new partial sums: grid (BH_, 8), each block sums 256 s-rows for all 256 d.
__global__ void znew_part(const float* __restrict__ SK, float* __restrict__ part){
    int z = blockIdx.x, c = blockIdx.y;
    int b = z / H_, h = z % H_;
    int d = threadIdx.x;
    const float* p = SK + (size_t)b*S_*E_ + h*D_ + d + (size_t)(c*256)*E_;
    float acc = 0.f;
    #pragma unroll 8
    for (int s=0; s<256; s++) acc += p[(size_t)s*E_];
    part[(z*8+c)*D_ + d] = acc;
}
__global__ void znew_fin(const float* __restrict__ part, const float* __restrict__ zvec,
                         float* __restrict__ out){
    int z = blockIdx.x, d = threadIdx.x;
    float a = zvec[(z%H_)*D_ + d];
    #pragma unroll
    for (int c=0;c<8;c++) a += part[(z*8+c)*D_ + d];
    out[z*D_ + d] = a;
}

// ================= launch =================
extern "C" void kernel_launch(void* const* d_in, const int* in_sizes, int n_in,
                              void* d_out, int out_size)
{
    const float* hs    = (const float*)d_in[0];
    const float* Wq    = (const float*)d_in[1];
    const float* Wk    = (const float*)d_in[2];
    const float* Wv    = (const float*)d_in[3];
    const float* Wo    = (const float*)d_in[4];
    const float* bo    = (const float*)d_in[5];
    const float* betas = (const float*)d_in[6];
    const float* memp  = (const float*)d_in[7];
    const float* zv    = (const float*)d_in[8];
    float* out = (float*)d_out;

    cudaFuncSetAttribute(tc_gemm, cudaFuncAttributeMaxDynamicSharedMemorySize, SMEM_BYTES);

#define GS(var, sym) cudaGetSymbolAddress((void**)&var, sym)
    bf16 *HSh,*HSl,*WqTh,*WqTl,*WkTh,*WkTl,*WvTh,*WvTl,*WoTh,*WoTl,*memTh,*memTl;
    bf16 *Qh,*Ql,*Kh,*Kl,*SQh,*SQl,*SKh,*SKl,*ABh,*ABl,*VTh,*VTl,*UTh,*UTl,*SKTh,*SKTl,*Ph,*Pl;
    float *Pf,*Vf,*Uf,*SKf,*AO,*Zq,*Zk,*Zp;
    GS(HSh,g_HSh); GS(HSl,g_HSl);
    GS(WqTh,g_WqTh); GS(WqTl,g_WqTl); GS(WkTh,g_WkTh); GS(WkTl,g_WkTl);
    GS(WvTh,g_WvTh); GS(WvTl,g_WvTl); GS(WoTh,g_WoTh); GS(WoTl,g_WoTl);
    GS(memTh,g_memTh); GS(memTl,g_memTl);
    GS(Qh,g_Qh); GS(Ql,g_Ql); GS(Kh,g_Kh); GS(Kl,g_Kl);
    GS(SQh,g_SQh); GS(SQl,g_SQl); GS(SKh,g_SKh); GS(SKl,g_SKl);
    GS(ABh,g_ABh); GS(ABl,g_ABl);
    GS(VTh,g_VTh); GS(VTl,g_VTl); GS(UTh,g_UTh); GS(UTl,g_UTl);
    GS(SKTh,g_SKTh); GS(SKTl,g_SKTl);
    GS(Ph,g_Ph); GS(Pl,g_Pl); GS(Pf,g_Pf);
    GS(Vf,g_Vf); GS(Uf,g_Uf); GS(SKf,g_SKf); GS(AO,g_AO);
    GS(Zq,g_Zq); GS(Zk,g_Zk); GS(Zp,g_Zpart);

    const long OUT_MEM = (long)B_*S_*E_;
    const long OUT_Z   = OUT_MEM + (long)B_*H_*D_*D_;
    dim3 t256(256), t328(32,8);

    // input conversions
    split_f32<<<MSZ/1024, t256>>>(hs, HSh, HSl, MSZ/4);
    transW<<<dim3(32,32), t328>>>(Wq, WqTh, WqTl);
    transW<<<dim3(32,32), t328>>>(Wk, WkTh, WkTl);
    transW<<<dim3(32,32), t328>>>(Wv, WvTh, WvTl);
    transW<<<dim3(32,32), t328>>>(Wo, WoTh, WoTl);
    transMem<<<dim3(8,8,H_), t328>>>(memp, memTh, memTl);

    // projections
    tc_gemm<<<dim3(8,64,1), t256, SMEM_BYTES>>>(HSh,HSl,WqTh,WqTl, E_,E_,E_,E_,
        0,0,0,0,0,0, EP_SIGQK,0, 0, Qh,Ql, SQh,SQl, 0,0,0,0);
    tc_gemm<<<dim3(8,64,1), t256, SMEM_BYTES>>>(HSh,HSl,WkTh,WkTl, E_,E_,E_,E_,
        0,0,0,0,0,0, EP_SIGQK,0, SKf, Kh,Kl, SKh,SKl, 0,0,0,0);
    tc_gemm<<<dim3(8,64,1), t256, SMEM_BYTES>>>(HSh,HSl,WvTh,WvTl, E_,E_,E_,E_,
        0,0,0,0,0,0, EP_F32,0, Vf, 0,0,0,0, 0,0,0,0);

    transBH<<<dim3(64,8,BH_), t328>>>(Vf, VTh, VTl);

    // scores (causal tile-skip) -> softmax(split) -> PV (K clamp)
    tc_gemm<<<dim3(16,16,BH_), t256, SMEM_BYTES>>>(Qh,Ql,Kh,Kl, D_, E_,E_,S_,
        (long)S_*E_, D_, (long)S_*E_, D_, (long)H_*S_*S_, (long)S_*S_,
        EP_F32,1, Pf, 0,0,0,0, 0,0,0,0);
    softmax_split<<<dim3(S_,BH_), t256>>>(Pf, Ph, Pl);
    tc_gemm<<<dim3(2,16,BH_), t256, SMEM_BYTES>>>(Ph,Pl,VTh,VTl, S_, S_,S_,E_,
        (long)H_*S_*S_, (long)S_*S_, (long)H_*D_*S_, (long)D_*S_, (long)S_*E_, (long)D_,
        EP_F32,2, AO, 0,0,0,0, 0,0,0,0);

    // sigma . z
    rowdot_split<<<BH_*S_/8, t256>>>(SQh, SQl, zv, Zq);
    rowdot_split<<<BH_*S_/8, t256>>>(SKh, SKl, zv, Zk);

    // A_mem + gate mix -> split AB
    tc_gemm<<<dim3(2,16,BH_), t256, SMEM_BYTES>>>(SQh,SQl,memTh,memTl, D_, E_,D_,E_,
        (long)S_*E_, D_, 0, (long)D_*D_, (long)S_*E_, (long)D_,
        EP_AMEM,0, 0, ABh,ABl, 0,0, Zq, AO, betas, 0);

    // U = V - delta
    tc_gemm<<<dim3(2,16,BH_), t256, SMEM_BYTES>>>(SKh,SKl,memTh,memTl, D_, E_,D_,E_,
        (long)S_*E_, D_, 0, (long)D_*D_, (long)S_*E_, (long)D_,
        EP_DELTA,0, Uf, 0,0,0,0, Zk, Vf, 0, 0);

    transBH<<<dim3(64,8,BH_), t328>>>(Uf, UTh, UTl);
    transBH<<<dim3(64,8,BH_), t328>>>(SKf, SKTh, SKTl);

    // mem_new = mem + SK^T @ U  (direct to d_out)
    tc_gemm<<<dim3(2,2,BH_), t256, SMEM_BYTES>>>(SKTh,SKTl,UTh,UTl, S_, S_,S_,D_,
        (long)H_*D_*S_, (long)D_*S_, (long)H_*D_*S_, (long)D_*S_, (long)H_*D_*D_, (long)D_*D_,
        EP_MEMUPD,0, out+OUT_MEM, 0,0,0,0, 0, memp, 0, 0);

    // z_new (deterministic two-stage reduction)
    znew_part<<<dim3(BH_,8), D_>>>(SKf, Zp);
    znew_fin<<<BH_, D_>>>(Zp, zv, out+OUT_Z);

    // out projection + bias
    tc_gemm<<<dim3(8,64,1), t256, SMEM_BYTES>>>(ABh,ABl,WoTh,WoTl, E_,E_,E_,E_,
        0,0,0,0,0,0, EP_BIAS,0, out, 0,0,0,0, 0,0,0, bo);
}

// round 6
// speedup vs baseline: 2.4323x; 1.0672x over previous
#include <cuda_runtime.h>
#include <cuda_bf16.h>
#include <cstdint>
#include <math.h>

#define B_ 4
#define S_ 2048
#define E_ 1024
#define H_ 4
#define D_ 256
#define BH_ 16
#define MSZ (B_*S_*E_)

typedef __nv_bfloat16 bf16;

// ================= device scratch =================
__device__ bf16 g_HSh[MSZ], g_HSl[MSZ];
__device__ bf16 g_WqTh[E_*E_], g_WqTl[E_*E_];
__device__ bf16 g_WkTh[E_*E_], g_WkTl[E_*E_];
__device__ bf16 g_WvTh[E_*E_], g_WvTl[E_*E_];
__device__ bf16 g_WoTh[E_*E_], g_WoTl[E_*E_];
__device__ bf16 g_memTh[H_*D_*D_], g_memTl[H_*D_*D_];
__device__ bf16 g_Qh[MSZ], g_Ql[MSZ], g_Kh[MSZ], g_Kl[MSZ];
__device__ bf16 g_SQh[MSZ], g_SQl[MSZ], g_SKh[MSZ], g_SKl[MSZ];
__device__ bf16 g_ABh[MSZ], g_ABl[MSZ];
__device__ bf16 g_VTh[MSZ], g_VTl[MSZ];
__device__ bf16 g_UTh[MSZ], g_UTl[MSZ];
__device__ bf16 g_SKTh[MSZ], g_SKTl[MSZ];
__device__ float g_Vf[MSZ], g_Uf[MSZ], g_SKf[MSZ], g_AO[MSZ];
__device__ float g_Zq[BH_*S_], g_Zk[BH_*S_];
__device__ float g_Zpart[BH_*8*D_];

// ================= helpers =================
__device__ __forceinline__ uint32_t smem_u32(const void* p){
    uint32_t a;
    asm("{ .reg .u64 t; cvta.to.shared.u64 t, %1; cvt.u32.u64 %0, t; }" : "=r"(a) : "l"(p));
    return a;
}
#define SWZ(o) ((o) ^ (((o) >> 3) & 0x70))

#define CP_ASYNC(daddr, gptr) \
    asm volatile("cp.async.cg.shared.global [%0], [%1], 16;" :: "r"(daddr), "l"(gptr) : "memory")
#define CP_COMMIT() asm volatile("cp.async.commit_group;" ::: "memory")
#define CP_WAIT(n)  asm volatile("cp.async.wait_group %0;" :: "n"(n) : "memory")

__device__ __forceinline__ void ldm_x4(uint32_t& r0, uint32_t& r1, uint32_t& r2, uint32_t& r3, uint32_t a){
    asm volatile("ldmatrix.sync.aligned.m8n8.x4.shared.b16 {%0,%1,%2,%3}, [%4];"
        : "=r"(r0), "=r"(r1), "=r"(r2), "=r"(r3) : "r"(a));
}
__device__ __forceinline__ void mma16816(float* c, const uint32_t* a, const uint32_t* b){
    asm volatile("mma.sync.aligned.m16n8k16.row.col.f32.bf16.bf16.f32 "
        "{%0,%1,%2,%3}, {%4,%5,%6,%7}, {%8,%9}, {%0,%1,%2,%3};"
        : "+f"(c[0]), "+f"(c[1]), "+f"(c[2]), "+f"(c[3])
        : "r"(a[0]), "r"(a[1]), "r"(a[2]), "r"(a[3]), "r"(b[0]), "r"(b[1]));
}

__device__ __forceinline__ void store_split(bf16* ph, bf16* pl, size_t i, float v){
    bf16 h = __float2bfloat16(v);
    ph[i] = h;
    pl[i] = __float2bfloat16(v - __bfloat162float(h));
}

enum { EP_F32=0, EP_SIGQK=1, EP_BIAS=2, EP_AMEM=3, EP_DELTA=4, EP_MEMUPD=5 };

#define STG_BYTES 65536
#define SMEM_BYTES (2*STG_BYTES)

// ================= HMMA GEMM: D = A @ B^T (unchanged, validated) =================
__global__ void __launch_bounds__(256,1) tc_gemm(
    const bf16* __restrict__ Ahg, const bf16* __restrict__ Alg,
    const bf16* __restrict__ Bhg, const bf16* __restrict__ Blg,
    int K, int lda, int ldb, int ldc,
    long sAb, long sAh, long sBb, long sBh, long sCb, long sCh,
    int mode, int causal,
    float* __restrict__ C, bf16* __restrict__ O1h, bf16* __restrict__ O1l,
    bf16* __restrict__ O2h, bf16* __restrict__ O2l,
    const float* __restrict__ rowdiv, const float* __restrict__ mix,
    const float* __restrict__ betas, const float* __restrict__ bias)
{
    extern __shared__ char smemc[];
    int z = blockIdx.z, bb = z / H_, hh = z % H_;
    int m0 = blockIdx.y*128, n0 = blockIdx.x*128;
    if (causal==1 && n0 > m0) return;
    int Keff = (causal==2) ? min(K, m0+128) : K;

    const bf16* Ah = Ahg + (size_t)bb*sAb + (size_t)hh*sAh;
    const bf16* Al = Alg + (size_t)bb*sAb + (size_t)hh*sAh;
    const bf16* Bh = Bhg + (size_t)bb*sBb + (size_t)hh*sBh;
    const bf16* Bl = Blg + (size_t)bb*sBb + (size_t)hh*sBh;
    size_t coff = (size_t)bb*sCb + (size_t)hh*sCh;

    int tid = threadIdx.x, wid = tid >> 5, lid = tid & 31;
    uint32_t sb = smem_u32(smemc);
    int wm = wid & 1, wn = wid >> 1;
    int mbase = wm*64, nbase = wn*32;

    float acc[4][4][4];
    #pragma unroll
    for (int i=0;i<4;i++)
        #pragma unroll
        for (int j=0;j<4;j++)
            #pragma unroll
            for (int r=0;r<4;r++) acc[i][j][r]=0.f;

    int nch = Keff >> 6;
    int row_l = tid >> 3, v_l = tid & 7;

    auto issue = [&](int ci, int s){
        int stg = s*STG_BYTES, kc0 = ci << 6;
        const bf16* ptrs[4] = {Ah, Al, Bh, Bl};
        int rb[4] = {m0, m0, n0, n0};
        int lds[4] = {lda, lda, ldb, ldb};
        #pragma unroll
        for (int bfi=0; bfi<4; bfi++){
            #pragma unroll
            for (int i=0;i<4;i++){
                int row = row_l + 32*i;
                uint32_t da = sb + stg + bfi*16384 + SWZ(row*128 + v_l*16);
                const void* gp = ptrs[bfi] + (size_t)(rb[bfi]+row)*lds[bfi] + kc0 + v_l*8;
                CP_ASYNC(da, gp);
            }
        }
        CP_COMMIT();
    };

    issue(0, 0);
    if (nch > 1) issue(1, 1);

    for (int ci=0; ci<nch; ci++){
        if (ci+1 < nch) { CP_WAIT(1); } else { CP_WAIT(0); }
        __syncthreads();
        int stg = (ci&1)*STG_BYTES;

        #pragma unroll
        for (int ks=0; ks<4; ks++){
            int colb = ks*32 + ((lid>>4)&1)*16;
            uint32_t ah[4][4], al[4][4];
            #pragma unroll
            for (int mt=0; mt<4; mt++){
                int row = mbase + mt*16 + (lid & 15);
                uint32_t off = SWZ(row*128 + colb);
                ldm_x4(ah[mt][0],ah[mt][1],ah[mt][2],ah[mt][3], sb+stg+off);
                ldm_x4(al[mt][0],al[mt][1],al[mt][2],al[mt][3], sb+stg+16384+off);
            }
            uint32_t bh[4][2], bl[4][2];
            #pragma unroll
            for (int g=0; g<2; g++){
                int row = nbase + g*16 + (lid & 7) + ((lid>>4)&1)*8;
                int cb2 = ks*32 + ((lid>>3)&1)*16;
                uint32_t off = SWZ(row*128 + cb2);
                uint32_t r0,r1,r2,r3;
                ldm_x4(r0,r1,r2,r3, sb+stg+32768+off);
                bh[2*g][0]=r0; bh[2*g][1]=r1; bh[2*g+1][0]=r2; bh[2*g+1][1]=r3;
                ldm_x4(r0,r1,r2,r3, sb+stg+49152+off);
                bl[2*g][0]=r0; bl[2*g][1]=r1; bl[2*g+1][0]=r2; bl[2*g+1][1]=r3;
            }
            #pragma unroll
            for (int mt=0; mt<4; mt++)
                #pragma unroll
                for (int nt=0; nt<4; nt++){
                    mma16816(acc[mt][nt], ah[mt], bh[nt]);
                    mma16816(acc[mt][nt], ah[mt], bl[nt]);
                    mma16816(acc[mt][nt], al[mt], bh[nt]);
                }
        }
        __syncthreads();
        if (ci+2 < nch) issue(ci+2, ci&1);
    }

    float* buf = (float*)smemc;
    int tg = lid >> 2, t4 = lid & 3;
    #pragma unroll
    for (int mt=0; mt<4; mt++)
        #pragma unroll
        for (int nt=0; nt<4; nt++)
            #pragma unroll
            for (int r=0; r<4; r++){
                int m = mbase + mt*16 + tg + (r>=2 ? 8 : 0);
                int c = nbase + nt*8 + t4*2 + (r&1);
                buf[m*132 + c] = acc[mt][nt][r];
            }
    __syncthreads();

    float gate = 0.f;
    if (mode == EP_AMEM) gate = 1.f/(1.f + __expf(-betas[hh]));

    #pragma unroll 4
    for (int e=0; e<64; e++){
        int flat = e*256 + tid;
        int row = flat >> 7, col = flat & 127;
        float v = buf[row*132 + col];
        int m = m0 + row, c = n0 + col;
        size_t idx = coff + (size_t)m*ldc + c;
        if (mode == EP_F32) {
            C[idx] = v;
        } else if (mode == EP_SIGQK) {
            store_split(O1h, O1l, idx, v);
            float sg = v > 0.f ? v + 1.f : __expf(v);
            store_split(O2h, O2l, idx, sg);
            if (C) C[idx] = sg;
        } else if (mode == EP_BIAS) {
            C[idx] = v + bias[c];
        } else if (mode == EP_AMEM) {
            float rinv = 1.f/(rowdiv[(size_t)z*S_ + m] + 1e-6f);
            float val = gate*(v*rinv) + (1.f-gate)*mix[idx];
            store_split(O1h, O1l, idx, val);
        } else if (mode == EP_DELTA) {
            float rinv = 1.f/(rowdiv[(size_t)z*S_ + m] + 1e-6f);
            C[idx] = mix[idx] - v*rinv;
        } else {
            float mv = mix[(size_t)hh*D_*D_ + (size_t)m*D_ + c];
            C[idx] = mv + v;
        }
    }
}

// ================= fused flash attention =================
// smem map (bytes):
//   [0, 64K)       stage0: S-phase {Qh,Ql,Kh,Kl} 16K each | PV-phase {VTh 32K, VTl 32K}
//   [64K, 128K)    stage1: same
//   [128K, 192K)   P: Ph_kc0 16K, Ph_kc1 16K, Pl_kc0 16K, Pl_kc1 16K
//   [192K, +3K)    m_s[128], l_s[128], red[4][128]
#define FA_P     131072
#define FA_STAT  196608
#define FA_SMEM  (196608 + 3072)

__global__ void __launch_bounds__(256,1) fa_kernel(
    const bf16* __restrict__ Qhg, const bf16* __restrict__ Qlg,
    const bf16* __restrict__ Khg, const bf16* __restrict__ Klg,
    const bf16* __restrict__ VThg, const bf16* __restrict__ VTlg,
    float* __restrict__ AO)
{
    extern __shared__ char smc[];
    uint32_t sb = smem_u32(smc);
    int bid = blockIdx.x;
    int z  = (bid>>1)&15;
    int mi = (bid&1) ? (bid>>5) : 15-(bid>>5);   // pair long with short tiles
    int bb = z / H_, hh = z % H_;
    int m0 = mi*128;

    int tid = threadIdx.x, wid = tid>>5, lid = tid&31;
    int wm = wid&1, wn = wid>>1;
    int tg = lid>>2, t4 = lid&3;

    const bf16* Qh_ = Qhg + (size_t)bb*S_*E_ + hh*D_;
    const bf16* Ql_ = Qlg + (size_t)bb*S_*E_ + hh*D_;
    const bf16* Kh_ = Khg + (size_t)bb*S_*E_ + hh*D_;
    const bf16* Kl_ = Klg + (size_t)bb*S_*E_ + hh*D_;
    const bf16* VTh_ = VThg + (size_t)z*D_*S_;
    const bf16* VTl_ = VTlg + (size_t)z*D_*S_;

    float* m_s = (float*)(smc + FA_STAT);
    float* l_s = (float*)(smc + FA_STAT + 512);
    float* red = (float*)(smc + FA_STAT + 1024);   // [4][128]

    if (tid < 128){ m_s[tid] = -1e30f; l_s[tid] = 0.f; }

    float acc_o[4][8][4];
    #pragma unroll
    for (int a=0;a<4;a++)
        #pragma unroll
        for (int b=0;b<8;b++)
            #pragma unroll
            for (int r=0;r<4;r++) acc_o[a][b][r]=0.f;
    __syncthreads();

    int row_l = tid>>3, v_l = tid&7;

    for (int j=0; j<=mi; j++){
        int jb = j*128;
        float acc_s[4][4][4];
        #pragma unroll
        for (int a=0;a<4;a++)
            #pragma unroll
            for (int b=0;b<4;b++)
                #pragma unroll
                for (int r=0;r<4;r++) acc_s[a][b][r]=0.f;

        auto issueS = [&](int c, int s){
            int stg = s*STG_BYTES, kc0 = c*64;
            #pragma unroll
            for (int i=0;i<4;i++){
                int row = row_l + 32*i;
                uint32_t o = SWZ(row*128 + v_l*16);
                CP_ASYNC(sb+stg+o,       Qh_ + (size_t)(m0+row)*E_ + kc0 + v_l*8);
                CP_ASYNC(sb+stg+16384+o, Ql_ + (size_t)(m0+row)*E_ + kc0 + v_l*8);
                CP_ASYNC(sb+stg+32768+o, Kh_ + (size_t)(jb+row)*E_ + kc0 + v_l*8);
                CP_ASYNC(sb+stg+49152+o, Kl_ + (size_t)(jb+row)*E_ + kc0 + v_l*8);
            }
            CP_COMMIT();
        };
        auto issueV = [&](int kc, int s){
            int stg = s*STG_BYTES;
            #pragma unroll
            for (int i=0;i<8;i++){
                int row = row_l + 32*i;      // d: 0..255
                uint32_t o = SWZ(row*128 + v_l*16);
                CP_ASYNC(sb+stg+o,       VTh_ + (size_t)row*S_ + jb + kc*64 + v_l*8);
                CP_ASYNC(sb+stg+32768+o, VTl_ + (size_t)row*S_ + jb + kc*64 + v_l*8);
            }
            CP_COMMIT();
        };

        // ---------- S = Q K^T (contraction d=256, 4 chunks) ----------
        issueS(0,0); issueS(1,1);
        for (int c=0;c<4;c++){
            if (c<3) { CP_WAIT(1); } else { CP_WAIT(0); }
            __syncthreads();
            int stg = (c&1)*STG_BYTES;
            #pragma unroll
            for (int ks=0; ks<4; ks++){
                uint32_t bh[4][2], bl[4][2];
                #pragma unroll
                for (int g=0; g<2; g++){
                    int row = wn*32 + g*16 + (lid&7) + ((lid>>4)&1)*8;
                    int cb2 = ks*32 + ((lid>>3)&1)*16;
                    uint32_t off = SWZ(row*128 + cb2);
                    uint32_t r0,r1,r2,r3;
                    ldm_x4(r0,r1,r2,r3, sb+stg+32768+off);
                    bh[2*g][0]=r0; bh[2*g][1]=r1; bh[2*g+1][0]=r2; bh[2*g+1][1]=r3;
                    ldm_x4(r0,r1,r2,r3, sb+stg+49152+off);
                    bl[2*g][0]=r0; bl[2*g][1]=r1; bl[2*g+1][0]=r2; bl[2*g+1][1]=r3;
                }
                #pragma unroll
                for (int mt=0; mt<4; mt++){
                    int row = wm*64 + mt*16 + (lid&15);
                    uint32_t colb = ks*32 + ((lid>>4)&1)*16;
                    uint32_t off = SWZ(row*128 + colb);
                    uint32_t ah[4], al[4];
                    ldm_x4(ah[0],ah[1],ah[2],ah[3], sb+stg+off);
                    ldm_x4(al[0],al[1],al[2],al[3], sb+stg+16384+off);
                    #pragma unroll
                    for (int nt=0;nt<4;nt++){
                        mma16816(acc_s[mt][nt], ah, bh[nt]);
                        mma16816(acc_s[mt][nt], ah, bl[nt]);
                        mma16816(acc_s[mt][nt], al, bh[nt]);
                    }
                }
            }
            __syncthreads();
            if (c==0) issueS(2,0);
            else if (c==1) issueS(3,1);
        }

        // prefetch V chunks (overlaps softmax below)
        issueV(0,0); issueV(1,1);

        // ---------- online softmax ----------
        if (j == mi){   // diagonal tile: causal mask
            #pragma unroll
            for (int mt=0; mt<4; mt++)
                #pragma unroll
                for (int nt=0; nt<4; nt++)
                    #pragma unroll
                    for (int r=0;r<4;r++){
                        int srow = wm*64 + mt*16 + tg + ((r>>1)&1)*8;
                        int scol = wn*32 + nt*8 + t4*2 + (r&1);
                        if (scol > srow) acc_s[mt][nt][r] = -1e30f;
                    }
        }
        // per-row partial max -> quad reduce -> red[wn][row]
        float rmax[4][2];
        #pragma unroll
        for (int mt=0; mt<4; mt++)
            #pragma unroll
            for (int hf=0; hf<2; hf++){
                float m = -1e30f;
                #pragma unroll
                for (int nt=0; nt<4; nt++){
                    m = fmaxf(m, acc_s[mt][nt][hf*2+0]);
                    m = fmaxf(m, acc_s[mt][nt][hf*2+1]);
                }
                m = fmaxf(m, __shfl_xor_sync(0xffffffffu, m, 1));
                m = fmaxf(m, __shfl_xor_sync(0xffffffffu, m, 2));
                rmax[mt][hf] = m;
            }
        if (t4 == 0){
            #pragma unroll
            for (int mt=0; mt<4; mt++)
                #pragma unroll
                for (int hf=0; hf<2; hf++)
                    red[wn*128 + wm*64 + mt*16 + tg + hf*8] = rmax[mt][hf];
        }
        __syncthreads();

        float mnew[4][2], alpha[4][2], rsum[4][2];
        #pragma unroll
        for (int mt=0; mt<4; mt++)
            #pragma unroll
            for (int hf=0; hf<2; hf++){
                int row = wm*64 + mt*16 + tg + hf*8;
                float rm = fmaxf(fmaxf(red[row], red[128+row]), fmaxf(red[256+row], red[384+row]));
                float mo = m_s[row];
                float mn = fmaxf(mo, rm);
                mnew[mt][hf] = mn;
                alpha[mt][hf] = __expf(mo - mn);
                rsum[mt][hf] = 0.f;
            }
        // exp + partial sums
        #pragma unroll
        for (int mt=0; mt<4; mt++)
            #pragma unroll
            for (int nt=0; nt<4; nt++)
                #pragma unroll
                for (int r=0;r<4;r++){
                    int hf = r>>1;
                    float p = __expf(acc_s[mt][nt][r] - mnew[mt][hf]);
                    acc_s[mt][nt][r] = p;
                    rsum[mt][hf] += p;
                }
        #pragma unroll
        for (int mt=0; mt<4; mt++)
            #pragma unroll
            for (int hf=0; hf<2; hf++){
                rsum[mt][hf] += __shfl_xor_sync(0xffffffffu, rsum[mt][hf], 1);
                rsum[mt][hf] += __shfl_xor_sync(0xffffffffu, rsum[mt][hf], 2);
            }
        __syncthreads();   // all reads of red (max) done
        if (t4 == 0){
            #pragma unroll
            for (int mt=0; mt<4; mt++)
                #pragma unroll
                for (int hf=0; hf<2; hf++)
                    red[wn*128 + wm*64 + mt*16 + tg + hf*8] = rsum[mt][hf];
        }
        // store P (unnormalized) as bf16 hi/lo into smem (A-tile format, 2 k-chunks)
        #pragma unroll
        for (int mt=0; mt<4; mt++)
            #pragma unroll
            for (int nt=0; nt<4; nt++)
                #pragma unroll
                for (int rp=0; rp<2; rp++){
                    int row = wm*64 + mt*16 + tg + rp*8;
                    int col = wn*32 + nt*8 + t4*2;
                    float p0 = acc_s[mt][nt][rp*2+0];
                    float p1 = acc_s[mt][nt][rp*2+1];
                    bf16 h0 = __float2bfloat16(p0);
                    bf16 h1 = __float2bfloat16(p1);
                    bf16 l0 = __float2bfloat16(p0 - __bfloat162float(h0));
                    bf16 l1 = __float2bfloat16(p1 - __bfloat162float(h1));
                    uint32_t o = (uint32_t)(col>>6)*16384u + SWZ((uint32_t)row*128 + (col&63)*2);
                    *(__nv_bfloat162*)(smc + FA_P + o)         = __nv_bfloat162(h0, h1);
                    *(__nv_bfloat162*)(smc + FA_P + 32768 + o) = __nv_bfloat162(l0, l1);
                }
        // rescale O
        #pragma unroll
        for (int mt=0; mt<4; mt++)
            #pragma unroll
            for (int nt=0; nt<8; nt++)
                #pragma unroll
                for (int r=0;r<4;r++)
                    acc_o[mt][nt][r] *= alpha[mt][r>>1];
        __syncthreads();   // P + rsum visible
        if (wn == 0 && t4 == 0){
            #pragma unroll
            for (int mt=0; mt<4; mt++)
                #pragma unroll
                for (int hf=0; hf<2; hf++){
                    int row = wm*64 + mt*16 + tg + hf*8;
                    float rs = red[row] + red[128+row] + red[256+row] + red[384+row];
                    l_s[row] = l_s[row]*alpha[mt][hf] + rs;
                    m_s[row] = mnew[mt][hf];
                }
        }

        // ---------- O += P V (contraction s=128, 2 chunks) ----------
        for (int kc=0; kc<2; kc++){
            if (kc==0) { CP_WAIT(1); } else { CP_WAIT(0); }
            __syncthreads();
            int stg = kc*STG_BYTES;
            uint32_t pb = FA_P + kc*16384;
            #pragma unroll
            for (int ks=0; ks<4; ks++){
                uint32_t bh[8][2], bl[8][2];
                #pragma unroll
                for (int g=0; g<4; g++){
                    int row = wn*64 + g*16 + (lid&7) + ((lid>>4)&1)*8;
                    int cb2 = ks*32 + ((lid>>3)&1)*16;
                    uint32_t off = SWZ(row*128 + cb2);
                    uint32_t r0,r1,r2,r3;
                    ldm_x4(r0,r1,r2,r3, sb+stg+off);
                    bh[2*g][0]=r0; bh[2*g][1]=r1; bh[2*g+1][0]=r2; bh[2*g+1][1]=r3;
                    ldm_x4(r0,r1,r2,r3, sb+stg+32768+off);
                    bl[2*g][0]=r0; bl[2*g][1]=r1; bl[2*g+1][0]=r2; bl[2*g+1][1]=r3;
                }
                #pragma unroll
                for (int mt=0; mt<4; mt++){
                    int row = wm*64 + mt*16 + (lid&15);
                    uint32_t colb = ks*32 + ((lid>>4)&1)*16;
                    uint32_t off = SWZ(row*128 + colb);
                    uint32_t ah[4], al[4];
                    ldm_x4(ah[0],ah[1],ah[2],ah[3], sb+pb+off);
                    ldm_x4(al[0],al[1],al[2],al[3], sb+pb+32768+off);
                    #pragma unroll
                    for (int nt=0;nt<8;nt++){
                        mma16816(acc_o[mt][nt], ah, bh[nt]);
                        mma16816(acc_o[mt][nt], ah, bl[nt]);
                        mma16816(acc_o[mt][nt], al, bh[nt]);
                    }
                }
            }
            __syncthreads();
        }
    }

    // ---------- normalize + store ----------
    __syncthreads();
    float* AOp = AO + (size_t)bb*S_*E_ + hh*D_;
    #pragma unroll
    for (int mt=0; mt<4; mt++)
        #pragma unroll
        for (int hf=0; hf<2; hf++){
            int row = wm*64 + mt*16 + tg + hf*8;
            float linv = 1.f/l_s[row];
            #pragma unroll
            for (int nt=0; nt<8; nt++){
                int col = wn*64 + nt*8 + t4*2;
                float2 v;
                v.x = acc_o[mt][nt][hf*2+0]*linv;
                v.y = acc_o[mt][nt][hf*2+1]*linv;
                *(float2*)(AOp + (size_t)(m0+row)*E_ + col) = v;
            }
        }
}

// ================= small kernels =================
__global__ void split_f32(const float* __restrict__ src, bf16* __restrict__ h, bf16* __restrict__ l, int n4){
    int i = blockIdx.x*blockDim.x + threadIdx.x;
    if (i >= n4) return;
    float4 v = ((const float4*)src)[i];
    size_t o = (size_t)i*4;
    store_split(h, l, o+0, v.x); store_split(h, l, o+1, v.y);
    store_split(h, l, o+2, v.z); store_split(h, l, o+3, v.w);
}

__global__ void transW(const float* __restrict__ W, bf16* __restrict__ Th, bf16* __restrict__ Tl){
    __shared__ float t[32][33];
    int k0 = blockIdx.x*32, n0 = blockIdx.y*32;
    int tx = threadIdx.x, ty = threadIdx.y;
    #pragma unroll
    for (int i=0;i<32;i+=8) t[ty+i][tx] = W[(size_t)(k0+ty+i)*E_ + n0+tx];
    __syncthreads();
    #pragma unroll
    for (int i=0;i<32;i+=8){
        size_t o = (size_t)(n0+ty+i)*E_ + k0+tx;
        store_split(Th, Tl, o, t[tx][ty+i]);
    }
}

__global__ void transBH(const float* __restrict__ X, bf16* __restrict__ Th, bf16* __restrict__ Tl){
    __shared__ float t[32][33];
    int z = blockIdx.z, b = z / H_, h = z % H_;
    int s0 = blockIdx.x*32, d0 = blockIdx.y*32;
    int tx = threadIdx.x, ty = threadIdx.y;
    const float* src = X + (size_t)b*S_*E_ + h*D_;
    #pragma unroll
    for (int i=0;i<32;i+=8) t[ty+i][tx] = src[(size_t)(s0+ty+i)*E_ + d0+tx];
    __syncthreads();
    #pragma unroll
    for (int i=0;i<32;i+=8){
        size_t o = (size_t)z*D_*S_ + (size_t)(d0+ty+i)*S_ + s0+tx;
        store_split(Th, Tl, o, t[tx][ty+i]);
    }
}

__global__ void transMem(const float* __restrict__ M, bf16* __restrict__ Th, bf16* __restrict__ Tl){
    __shared__ float t[32][33];
    int h = blockIdx.z;
    int d0 = blockIdx.x*32, e0 = blockIdx.y*32;
    int tx = threadIdx.x, ty = threadIdx.y;
    #pragma unroll
    for (int i=0;i<32;i+=8) t[ty+i][tx] = M[(size_t)h*D_*D_ + (size_t)(d0+ty+i)*D_ + e0+tx];
    __syncthreads();
    #pragma unroll
    for (int i=0;i<32;i+=8){
        size_t o = (size_t)h*D_*D_ + (size_t)(e0+ty+i)*D_ + d0+tx;
        store_split(Th, Tl, o, t[tx][ty+i]);
    }
}

__global__ void rowdot_split(const bf16* __restrict__ Hh, const bf16* __restrict__ Hl,
                             const float* __restrict__ zvec, float* __restrict__ out){
    int w = threadIdx.x >> 5, lane = threadIdx.x & 31;
    int r = blockIdx.x*8 + w;
    int z = r / S_, s = r % S_;
    int b = z / H_, h = z % H_;
    size_t base = (size_t)(b*S_+s)*E_ + h*D_;
    const float* zp = zvec + h*D_;
    float acc = 0.f;
    #pragma unroll
    for (int d=lane; d<D_; d+=32)
        acc += (__bfloat162float(Hh[base+d]) + __bfloat162float(Hl[base+d])) * zp[d];
    #pragma unroll
    for (int o=16;o;o>>=1) acc += __shfl_xor_sync(0xffffffffu, acc, o);
    if (lane==0) out[r] = acc;
}

__global__ void znew_part(const float* __restrict__ SK, float* __restrict__ part){
    int z = blockIdx.x, c = blockIdx.y;
    int b = z / H_, h = z % H_;
    int d = threadIdx.x;
    const float* p = SK + (size_t)b*S_*E_ + h*D_ + d + (size_t)(c*256)*E_;
    float acc = 0.f;
    #pragma unroll 8
    for (int s=0; s<256; s++) acc += p[(size_t)s*E_];
    part[(z*8+c)*D_ + d] = acc;
}
__global__ void znew_fin(const float* __restrict__ part, const float* __restrict__ zvec,
                         float* __restrict__ out){
    int z = blockIdx.x, d = threadIdx.x;
    float a = zvec[(z%H_)*D_ + d];
    #pragma unroll
    for (int c=0;c<8;c++) a += part[(z*8+c)*D_ + d];
    out[z*D_ + d] = a;
}

// ================= launch =================
extern "C" void kernel_launch(void* const* d_in, const int* in_sizes, int n_in,
                              void* d_out, int out_size)
{
    const float* hs    = (const float*)d_in[0];
    const float* Wq    = (const float*)d_in[1];
    const float* Wk    = (const float*)d_in[2];
    const float* Wv    = (const float*)d_in[3];
    const float* Wo    = (const float*)d_in[4];
    const float* bo    = (const float*)d_in[5];
    const float* betas = (const float*)d_in[6];
    const float* memp  = (const float*)d_in[7];
    const float* zv    = (const float*)d_in[8];
    float* out = (float*)d_out;

    cudaFuncSetAttribute(tc_gemm, cudaFuncAttributeMaxDynamicSharedMemorySize, SMEM_BYTES);
    cudaFuncSetAttribute(fa_kernel, cudaFuncAttributeMaxDynamicSharedMemorySize, FA_SMEM);

#define GS(var, sym) cudaGetSymbolAddress((void**)&var, sym)
    bf16 *HSh,*HSl,*WqTh,*WqTl,*WkTh,*WkTl,*WvTh,*WvTl,*WoTh,*WoTl,*memTh,*memTl;
    bf16 *Qh,*Ql,*Kh,*Kl,*SQh,*SQl,*SKh,*SKl,*ABh,*ABl,*VTh,*VTl,*UTh,*UTl,*SKTh,*SKTl;
    float *Vf,*Uf,*SKf,*AO,*Zq,*Zk,*Zp;
    GS(HSh,g_HSh); GS(HSl,g_HSl);
    GS(WqTh,g_WqTh); GS(WqTl,g_WqTl); GS(WkTh,g_WkTh); GS(WkTl,g_WkTl);
    GS(WvTh,g_WvTh); GS(WvTl,g_WvTl); GS(WoTh,g_WoTh); GS(WoTl,g_WoTl);
    GS(memTh,g_memTh); GS(memTl,g_memTl);
    GS(Qh,g_Qh); GS(Ql,g_Ql); GS(Kh,g_Kh); GS(Kl,g_Kl);
    GS(SQh,g_SQh); GS(SQl,g_SQl); GS(SKh,g_SKh); GS(SKl,g_SKl);
    GS(ABh,g_ABh); GS(ABl,g_ABl);
    GS(VTh,g_VTh); GS(VTl,g_VTl); GS(UTh,g_UTh); GS(UTl,g_UTl);
    GS(SKTh,g_SKTh); GS(SKTl,g_SKTl);
    GS(Vf,g_Vf); GS(Uf,g_Uf); GS(SKf,g_SKf); GS(AO,g_AO);
    GS(Zq,g_Zq); GS(Zk,g_Zk); GS(Zp,g_Zpart);

    const long OUT_MEM = (long)B_*S_*E_;
    const long OUT_Z   = OUT_MEM + (long)B_*H_*D_*D_;
    dim3 t256(256), t328(32,8);

    // input conversions
    split_f32<<<MSZ/1024, t256>>>(hs, HSh, HSl, MSZ/4);
    transW<<<dim3(32,32), t328>>>(Wq, WqTh, WqTl);
    transW<<<dim3(32,32), t328>>>(Wk, WkTh, WkTl);
    transW<<<dim3(32,32), t328>>>(Wv, WvTh, WvTl);
    transW<<<dim3(32,32), t328>>>(Wo, WoTh, WoTl);
    transMem<<<dim3(8,8,H_), t328>>>(memp, memTh, memTl);

    // projections
    tc_gemm<<<dim3(8,64,1), t256, SMEM_BYTES>>>(HSh,HSl,WqTh,WqTl, E_,E_,E_,E_,
        0,0,0,0,0,0, EP_SIGQK,0, 0, Qh,Ql, SQh,SQl, 0,0,0,0);
    tc_gemm<<<dim3(8,64,1), t256, SMEM_BYTES>>>(HSh,HSl,WkTh,WkTl, E_,E_,E_,E_,
        0,0,0,0,0,0, EP_SIGQK,0, SKf, Kh,Kl, SKh,SKl, 0,0,0,0);
    tc_gemm<<<dim3(8,64,1), t256, SMEM_BYTES>>>(HSh,HSl,WvTh,WvTl, E_,E_,E_,E_,
        0,0,0,0,0,0, EP_F32,0, Vf, 0,0,0,0, 0,0,0,0);

    transBH<<<dim3(64,8,BH_), t328>>>(Vf, VTh, VTl);

    // fused attention: scores + online softmax + PV
    fa_kernel<<<256, t256, FA_SMEM>>>(Qh,Ql,Kh,Kl,VTh,VTl, AO);

    // sigma . z
    rowdot_split<<<BH_*S_/8, t256>>>(SQh, SQl, zv, Zq);
    rowdot_split<<<BH_*S_/8, t256>>>(SKh, SKl, zv, Zk);

    // A_mem + gate mix -> split AB
    tc_gemm<<<dim3(2,16,BH_), t256, SMEM_BYTES>>>(SQh,SQl,memTh,memTl, D_, E_,D_,E_,
        (long)S_*E_, D_, 0, (long)D_*D_, (long)S_*E_, (long)D_,
        EP_AMEM,0, 0, ABh,ABl, 0,0, Zq, AO, betas, 0);

    // U = V - delta
    tc_gemm<<<dim3(2,16,BH_), t256, SMEM_BYTES>>>(SKh,SKl,memTh,memTl, D_, E_,D_,E_,
        (long)S_*E_, D_, 0, (long)D_*D_, (long)S_*E_, (long)D_,
        EP_DELTA,0, Uf, 0,0,0,0, Zk, Vf, 0, 0);

    transBH<<<dim3(64,8,BH_), t328>>>(Uf, UTh, UTl);
    transBH<<<dim3(64,8,BH_), t328>>>(SKf, SKTh, SKTl);

    // mem_new = mem + SK^T @ U
    tc_gemm<<<dim3(2,2,BH_), t256, SMEM_BYTES>>>(SKTh,SKTl,UTh,UTl, S_, S_,S_,D_,
        (long)H_*D_*S_, (long)D_*S_, (long)H_*D_*S_, (long)D_*S_, (long)H_*D_*D_, (long)D_*D_,
        EP_MEMUPD,0, out+OUT_MEM, 0,0,0,0, 0, memp, 0, 0);

    // z_new
    znew_part<<<dim3(BH_,8), D_>>>(SKf, Zp);
    znew_fin<<<BH_, D_>>>(Zp, zv, out+OUT_Z);

    // out projection + bias
    tc_gemm<<<dim3(8,64,1), t256, SMEM_BYTES>>>(ABh,ABl,WoTh,WoTl, E_,E_,E_,E_,
        0,0,0,0,0,0, EP_BIAS,0, out, 0,0,0,0, 0,0,0, bo);
}

// round 7
// speedup vs baseline: 2.6884x; 1.1053x over previous
#include <cuda_runtime.h>
#include <cuda_bf16.h>
#include <cstdint>
#include <math.h>

#define B_ 4
#define S_ 2048
#define E_ 1024
#define H_ 4
#define D_ 256
#define BH_ 16
#define MSZ (B_*S_*E_)

typedef __nv_bfloat16 bf16;

// ================= device scratch =================
__device__ bf16 g_HSh[MSZ], g_HSl[MSZ];
__device__ bf16 g_WqTh[E_*E_], g_WqTl[E_*E_];
__device__ bf16 g_WkTh[E_*E_], g_WkTl[E_*E_];
__device__ bf16 g_WvTh[E_*E_], g_WvTl[E_*E_];
__device__ bf16 g_WoTh[E_*E_], g_WoTl[E_*E_];
__device__ bf16 g_memTh[H_*D_*D_], g_memTl[H_*D_*D_];
__device__ bf16 g_Qh[MSZ], g_Ql[MSZ], g_Kh[MSZ], g_Kl[MSZ];
__device__ bf16 g_SQh[MSZ], g_SQl[MSZ], g_SKh[MSZ], g_SKl[MSZ];
__device__ bf16 g_ABh[MSZ], g_ABl[MSZ];
__device__ bf16 g_VTh[MSZ], g_VTl[MSZ];
__device__ bf16 g_UTh[MSZ], g_UTl[MSZ];
__device__ bf16 g_SKTh[MSZ], g_SKTl[MSZ];
__device__ float g_Vf[MSZ], g_Uf[MSZ], g_SKf[MSZ], g_AO[MSZ];
__device__ float g_Zq[BH_*S_], g_Zk[BH_*S_];
__device__ float g_Zpart[BH_*8*D_];

// ================= helpers =================
__device__ __forceinline__ uint32_t smem_u32(const void* p){
    uint32_t a;
    asm("{ .reg .u64 t; cvta.to.shared.u64 t, %1; cvt.u32.u64 %0, t; }" : "=r"(a) : "l"(p));
    return a;
}
#define SWZ(o) ((o) ^ (((o) >> 3) & 0x70))

#define CP_ASYNC(daddr, gptr) \
    asm volatile("cp.async.cg.shared.global [%0], [%1], 16;" :: "r"(daddr), "l"(gptr) : "memory")
#define CP_COMMIT() asm volatile("cp.async.commit_group;" ::: "memory")
#define CP_WAIT(n)  asm volatile("cp.async.wait_group %0;" :: "n"(n) : "memory")

__device__ __forceinline__ void ldm_x4(uint32_t& r0, uint32_t& r1, uint32_t& r2, uint32_t& r3, uint32_t a){
    asm volatile("ldmatrix.sync.aligned.m8n8.x4.shared.b16 {%0,%1,%2,%3}, [%4];"
        : "=r"(r0), "=r"(r1), "=r"(r2), "=r"(r3) : "r"(a));
}
__device__ __forceinline__ void mma16816(float* c, const uint32_t* a, const uint32_t* b){
    asm volatile("mma.sync.aligned.m16n8k16.row.col.f32.bf16.bf16.f32 "
        "{%0,%1,%2,%3}, {%4,%5,%6,%7}, {%8,%9}, {%0,%1,%2,%3};"
        : "+f"(c[0]), "+f"(c[1]), "+f"(c[2]), "+f"(c[3])
        : "r"(a[0]), "r"(a[1]), "r"(a[2]), "r"(a[3]), "r"(b[0]), "r"(b[1]));
}

__device__ __forceinline__ void store_split(bf16* ph, bf16* pl, size_t i, float v){
    bf16 h = __float2bfloat16(v);
    ph[i] = h;
    pl[i] = __float2bfloat16(v - __bfloat162float(h));
}

enum { EP_F32=0, EP_SIGQK=1, EP_BIAS=2, EP_AMEM=3, EP_DELTA=4, EP_MEMUPD=5 };

// ================= 512-thread HMMA GEMM: D = A @ B^T =================
// Block tile 128x256, K-chunk 64, 2-stage cp.async. 16 warps = 2(m) x 8(n),
// each warp the validated 64x32 micro-schedule.
// Stage layout (96KB): Ah 16K | Al 16K | Bh 32K | Bl 32K
#define G5_STG 98304
#define G5_SMEM (2*G5_STG)

__global__ void __launch_bounds__(512,1) tc_gemm(
    const bf16* __restrict__ Ahg, const bf16* __restrict__ Alg,
    const bf16* __restrict__ Bhg, const bf16* __restrict__ Blg,
    int K, int lda, int ldb, int ldc,
    long sAb, long sAh, long sBb, long sBh, long sCb, long sCh,
    int mode,
    float* __restrict__ C, bf16* __restrict__ O1h, bf16* __restrict__ O1l,
    bf16* __restrict__ O2h, bf16* __restrict__ O2l,
    const float* __restrict__ rowdiv, const float* __restrict__ mix,
    const float* __restrict__ betas, const float* __restrict__ bias)
{
    extern __shared__ char smemc[];
    int z = blockIdx.z, bb = z / H_, hh = z % H_;
    int m0 = blockIdx.y*128, n0 = blockIdx.x*256;

    const bf16* Ah = Ahg + (size_t)bb*sAb + (size_t)hh*sAh;
    const bf16* Al = Alg + (size_t)bb*sAb + (size_t)hh*sAh;
    const bf16* Bh = Bhg + (size_t)bb*sBb + (size_t)hh*sBh;
    const bf16* Bl = Blg + (size_t)bb*sBb + (size_t)hh*sBh;
    size_t coff = (size_t)bb*sCb + (size_t)hh*sCh;

    int tid = threadIdx.x, wid = tid >> 5, lid = tid & 31;
    uint32_t sb = smem_u32(smemc);
    int wm = wid & 1, wn = wid >> 1;         // 2 x 8 warp grid
    int mbase = wm*64, nbase = wn*32;

    float acc[4][4][4];
    #pragma unroll
    for (int i=0;i<4;i++)
        #pragma unroll
        for (int j=0;j<4;j++)
            #pragma unroll
            for (int r=0;r<4;r++) acc[i][j][r]=0.f;

    int nch = K >> 6;
    int row_l = tid >> 3, v_l = tid & 7;     // 64 rows/pass, 8 x 16B cols

    auto issue = [&](int ci, int s){
        int stg = s*G5_STG, kc0 = ci << 6;
        // A hi/lo: 128 rows
        #pragma unroll
        for (int i=0;i<2;i++){
            int row = row_l + 64*i;
            uint32_t o = SWZ(row*128 + v_l*16);
            CP_ASYNC(sb+stg+o,       Ah + (size_t)(m0+row)*lda + kc0 + v_l*8);
            CP_ASYNC(sb+stg+16384+o, Al + (size_t)(m0+row)*lda + kc0 + v_l*8);
        }
        // B hi/lo: 256 rows
        #pragma unroll
        for (int i=0;i<4;i++){
            int row = row_l + 64*i;
            uint32_t o = SWZ(row*128 + v_l*16);
            CP_ASYNC(sb+stg+32768+o, Bh + (size_t)(n0+row)*ldb + kc0 + v_l*8);
            CP_ASYNC(sb+stg+65536+o, Bl + (size_t)(n0+row)*ldb + kc0 + v_l*8);
        }
        CP_COMMIT();
    };

    issue(0, 0);
    if (nch > 1) issue(1, 1);

    for (int ci=0; ci<nch; ci++){
        if (ci+1 < nch) { CP_WAIT(1); } else { CP_WAIT(0); }
        __syncthreads();
        int stg = (ci&1)*G5_STG;

        #pragma unroll
        for (int ks=0; ks<4; ks++){
            int colb = ks*32 + ((lid>>4)&1)*16;
            uint32_t ah[4][4], al[4][4];
            #pragma unroll
            for (int mt=0; mt<4; mt++){
                int row = mbase + mt*16 + (lid & 15);
                uint32_t off = SWZ(row*128 + colb);
                ldm_x4(ah[mt][0],ah[mt][1],ah[mt][2],ah[mt][3], sb+stg+off);
                ldm_x4(al[mt][0],al[mt][1],al[mt][2],al[mt][3], sb+stg+16384+off);
            }
            uint32_t bh[4][2], bl[4][2];
            #pragma unroll
            for (int g=0; g<2; g++){
                int row = nbase + g*16 + (lid & 7) + ((lid>>4)&1)*8;
                int cb2 = ks*32 + ((lid>>3)&1)*16;
                uint32_t off = SWZ(row*128 + cb2);
                uint32_t r0,r1,r2,r3;
                ldm_x4(r0,r1,r2,r3, sb+stg+32768+off);
                bh[2*g][0]=r0; bh[2*g][1]=r1; bh[2*g+1][0]=r2; bh[2*g+1][1]=r3;
                ldm_x4(r0,r1,r2,r3, sb+stg+65536+off);
                bl[2*g][0]=r0; bl[2*g][1]=r1; bl[2*g+1][0]=r2; bl[2*g+1][1]=r3;
            }
            #pragma unroll
            for (int mt=0; mt<4; mt++)
                #pragma unroll
                for (int nt=0; nt<4; nt++){
                    mma16816(acc[mt][nt], ah[mt], bh[nt]);
                    mma16816(acc[mt][nt], ah[mt], bl[nt]);
                    mma16816(acc[mt][nt], al[mt], bh[nt]);
                }
        }
        __syncthreads();
        if (ci+2 < nch) issue(ci+2, ci&1);
    }

    // ---- epilogue: stage through smem (pitch 260), coalesced modal stores ----
    float* buf = (float*)smemc;              // 128 x 260 floats = 133KB
    int tg = lid >> 2, t4 = lid & 3;
    #pragma unroll
    for (int mt=0; mt<4; mt++)
        #pragma unroll
        for (int nt=0; nt<4; nt++)
            #pragma unroll
            for (int r=0; r<4; r++){
                int m = mbase + mt*16 + tg + (r>=2 ? 8 : 0);
                int c = nbase + nt*8 + t4*2 + (r&1);
                buf[m*260 + c] = acc[mt][nt][r];
            }
    __syncthreads();

    float gate = 0.f;
    if (mode == EP_AMEM) gate = 1.f/(1.f + __expf(-betas[hh]));

    #pragma unroll 4
    for (int e=0; e<64; e++){
        int flat = e*512 + tid;
        int row = flat >> 8, col = flat & 255;
        float v = buf[row*260 + col];
        int m = m0 + row, c = n0 + col;
        size_t idx = coff + (size_t)m*ldc + c;
        if (mode == EP_F32) {
            C[idx] = v;
        } else if (mode == EP_SIGQK) {
            store_split(O1h, O1l, idx, v);
            float sg = v > 0.f ? v + 1.f : __expf(v);
            store_split(O2h, O2l, idx, sg);
            if (C) C[idx] = sg;
        } else if (mode == EP_BIAS) {
            C[idx] = v + bias[c];
        } else if (mode == EP_AMEM) {
            float rinv = 1.f/(rowdiv[(size_t)z*S_ + m] + 1e-6f);
            float val = gate*(v*rinv) + (1.f-gate)*mix[idx];
            store_split(O1h, O1l, idx, val);
        } else if (mode == EP_DELTA) {
            float rinv = 1.f/(rowdiv[(size_t)z*S_ + m] + 1e-6f);
            C[idx] = mix[idx] - v*rinv;
        } else {
            float mv = mix[(size_t)hh*D_*D_ + (size_t)m*D_ + c];
            C[idx] = mv + v;
        }
    }
}

// ================= fused flash attention (unchanged, validated) =================
#define STG_BYTES 65536
#define FA_P     131072
#define FA_STAT  196608
#define FA_SMEM  (196608 + 3072)

__global__ void __launch_bounds__(256,1) fa_kernel(
    const bf16* __restrict__ Qhg, const bf16* __restrict__ Qlg,
    const bf16* __restrict__ Khg, const bf16* __restrict__ Klg,
    const bf16* __restrict__ VThg, const bf16* __restrict__ VTlg,
    float* __restrict__ AO)
{
    extern __shared__ char smc[];
    uint32_t sb = smem_u32(smc);
    int bid = blockIdx.x;
    int z  = (bid>>1)&15;
    int mi = (bid&1) ? (bid>>5) : 15-(bid>>5);
    int bb = z / H_, hh = z % H_;
    int m0 = mi*128;

    int tid = threadIdx.x, wid = tid>>5, lid = tid&31;
    int wm = wid&1, wn = wid>>1;
    int tg = lid>>2, t4 = lid&3;

    const bf16* Qh_ = Qhg + (size_t)bb*S_*E_ + hh*D_;
    const bf16* Ql_ = Qlg + (size_t)bb*S_*E_ + hh*D_;
    const bf16* Kh_ = Khg + (size_t)bb*S_*E_ + hh*D_;
    const bf16* Kl_ = Klg + (size_t)bb*S_*E_ + hh*D_;
    const bf16* VTh_ = VThg + (size_t)z*D_*S_;
    const bf16* VTl_ = VTlg + (size_t)z*D_*S_;

    float* m_s = (float*)(smc + FA_STAT);
    float* l_s = (float*)(smc + FA_STAT + 512);
    float* red = (float*)(smc + FA_STAT + 1024);

    if (tid < 128){ m_s[tid] = -1e30f; l_s[tid] = 0.f; }

    float acc_o[4][8][4];
    #pragma unroll
    for (int a=0;a<4;a++)
        #pragma unroll
        for (int b=0;b<8;b++)
            #pragma unroll
            for (int r=0;r<4;r++) acc_o[a][b][r]=0.f;
    __syncthreads();

    int row_l = tid>>3, v_l = tid&7;

    for (int j=0; j<=mi; j++){
        int jb = j*128;
        float acc_s[4][4][4];
        #pragma unroll
        for (int a=0;a<4;a++)
            #pragma unroll
            for (int b=0;b<4;b++)
                #pragma unroll
                for (int r=0;r<4;r++) acc_s[a][b][r]=0.f;

        auto issueS = [&](int c, int s){
            int stg = s*STG_BYTES, kc0 = c*64;
            #pragma unroll
            for (int i=0;i<4;i++){
                int row = row_l + 32*i;
                uint32_t o = SWZ(row*128 + v_l*16);
                CP_ASYNC(sb+stg+o,       Qh_ + (size_t)(m0+row)*E_ + kc0 + v_l*8);
                CP_ASYNC(sb+stg+16384+o, Ql_ + (size_t)(m0+row)*E_ + kc0 + v_l*8);
                CP_ASYNC(sb+stg+32768+o, Kh_ + (size_t)(jb+row)*E_ + kc0 + v_l*8);
                CP_ASYNC(sb+stg+49152+o, Kl_ + (size_t)(jb+row)*E_ + kc0 + v_l*8);
            }
            CP_COMMIT();
        };
        auto issueV = [&](int kc, int s){
            int stg = s*STG_BYTES;
            #pragma unroll
            for (int i=0;i<8;i++){
                int row = row_l + 32*i;
                uint32_t o = SWZ(row*128 + v_l*16);
                CP_ASYNC(sb+stg+o,       VTh_ + (size_t)row*S_ + jb + kc*64 + v_l*8);
                CP_ASYNC(sb+stg+32768+o, VTl_ + (size_t)row*S_ + jb + kc*64 + v_l*8);
            }
            CP_COMMIT();
        };

        issueS(0,0); issueS(1,1);
        for (int c=0;c<4;c++){
            if (c<3) { CP_WAIT(1); } else { CP_WAIT(0); }
            __syncthreads();
            int stg = (c&1)*STG_BYTES;
            #pragma unroll
            for (int ks=0; ks<4; ks++){
                uint32_t bh[4][2], bl[4][2];
                #pragma unroll
                for (int g=0; g<2; g++){
                    int row = wn*32 + g*16 + (lid&7) + ((lid>>4)&1)*8;
                    int cb2 = ks*32 + ((lid>>3)&1)*16;
                    uint32_t off = SWZ(row*128 + cb2);
                    uint32_t r0,r1,r2,r3;
                    ldm_x4(r0,r1,r2,r3, sb+stg+32768+off);
                    bh[2*g][0]=r0; bh[2*g][1]=r1; bh[2*g+1][0]=r2; bh[2*g+1][1]=r3;
                    ldm_x4(r0,r1,r2,r3, sb+stg+49152+off);
                    bl[2*g][0]=r0; bl[2*g][1]=r1; bl[2*g+1][0]=r2; bl[2*g+1][1]=r3;
                }
                #pragma unroll
                for (int mt=0; mt<4; mt++){
                    int row = wm*64 + mt*16 + (lid&15);
                    uint32_t colb = ks*32 + ((lid>>4)&1)*16;
                    uint32_t off = SWZ(row*128 + colb);
                    uint32_t ah[4], al[4];
                    ldm_x4(ah[0],ah[1],ah[2],ah[3], sb+stg+off);
                    ldm_x4(al[0],al[1],al[2],al[3], sb+stg+16384+off);
                    #pragma unroll
                    for (int nt=0;nt<4;nt++){
                        mma16816(acc_s[mt][nt], ah, bh[nt]);
                        mma16816(acc_s[mt][nt], ah, bl[nt]);
                        mma16816(acc_s[mt][nt], al, bh[nt]);
                    }
                }
            }
            __syncthreads();
            if (c==0) issueS(2,0);
            else if (c==1) issueS(3,1);
        }

        issueV(0,0); issueV(1,1);

        if (j == mi){
            #pragma unroll
            for (int mt=0; mt<4; mt++)
                #pragma unroll
                for (int nt=0; nt<4; nt++)
                    #pragma unroll
                    for (int r=0;r<4;r++){
                        int srow = wm*64 + mt*16 + tg + ((r>>1)&1)*8;
                        int scol = wn*32 + nt*8 + t4*2 + (r&1);
                        if (scol > srow) acc_s[mt][nt][r] = -1e30f;
                    }
        }
        float rmax[4][2];
        #pragma unroll
        for (int mt=0; mt<4; mt++)
            #pragma unroll
            for (int hf=0; hf<2; hf++){
                float m = -1e30f;
                #pragma unroll
                for (int nt=0; nt<4; nt++){
                    m = fmaxf(m, acc_s[mt][nt][hf*2+0]);
                    m = fmaxf(m, acc_s[mt][nt][hf*2+1]);
                }
                m = fmaxf(m, __shfl_xor_sync(0xffffffffu, m, 1));
                m = fmaxf(m, __shfl_xor_sync(0xffffffffu, m, 2));
                rmax[mt][hf] = m;
            }
        if (t4 == 0){
            #pragma unroll
            for (int mt=0; mt<4; mt++)
                #pragma unroll
                for (int hf=0; hf<2; hf++)
                    red[wn*128 + wm*64 + mt*16 + tg + hf*8] = rmax[mt][hf];
        }
        __syncthreads();

        float mnew[4][2], alpha[4][2], rsum[4][2];
        #pragma unroll
        for (int mt=0; mt<4; mt++)
            #pragma unroll
            for (int hf=0; hf<2; hf++){
                int row = wm*64 + mt*16 + tg + hf*8;
                float rm = fmaxf(fmaxf(red[row], red[128+row]), fmaxf(red[256+row], red[384+row]));
                float mo = m_s[row];
                float mn = fmaxf(mo, rm);
                mnew[mt][hf] = mn;
                alpha[mt][hf] = __expf(mo - mn);
                rsum[mt][hf] = 0.f;
            }
        #pragma unroll
        for (int mt=0; mt<4; mt++)
            #pragma unroll
            for (int nt=0; nt<4; nt++)
                #pragma unroll
                for (int r=0;r<4;r++){
                    int hf = r>>1;
                    float p = __expf(acc_s[mt][nt][r] - mnew[mt][hf]);
                    acc_s[mt][nt][r] = p;
                    rsum[mt][hf] += p;
                }
        #pragma unroll
        for (int mt=0; mt<4; mt++)
            #pragma unroll
            for (int hf=0; hf<2; hf++){
                rsum[mt][hf] += __shfl_xor_sync(0xffffffffu, rsum[mt][hf], 1);
                rsum[mt][hf] += __shfl_xor_sync(0xffffffffu, rsum[mt][hf], 2);
            }
        __syncthreads();
        if (t4 == 0){
            #pragma unroll
            for (int mt=0; mt<4; mt++)
                #pragma unroll
                for (int hf=0; hf<2; hf++)
                    red[wn*128 + wm*64 + mt*16 + tg + hf*8] = rsum[mt][hf];
        }
        #pragma unroll
        for (int mt=0; mt<4; mt++)
            #pragma unroll
            for (int nt=0; nt<4; nt++)
                #pragma unroll
                for (int rp=0; rp<2; rp++){
                    int row = wm*64 + mt*16 + tg + rp*8;
                    int col = wn*32 + nt*8 + t4*2;
                    float p0 = acc_s[mt][nt][rp*2+0];
                    float p1 = acc_s[mt][nt][rp*2+1];
                    bf16 h0 = __float2bfloat16(p0);
                    bf16 h1 = __float2bfloat16(p1);
                    bf16 l0 = __float2bfloat16(p0 - __bfloat162float(h0));
                    bf16 l1 = __float2bfloat16(p1 - __bfloat162float(h1));
                    uint32_t o = (uint32_t)(col>>6)*16384u + SWZ((uint32_t)row*128 + (col&63)*2);
                    *(__nv_bfloat162*)(smc + FA_P + o)         = __nv_bfloat162(h0, h1);
                    *(__nv_bfloat162*)(smc + FA_P + 32768 + o) = __nv_bfloat162(l0, l1);
                }
        #pragma unroll
        for (int mt=0; mt<4; mt++)
            #pragma unroll
            for (int nt=0; nt<8; nt++)
                #pragma unroll
                for (int r=0;r<4;r++)
                    acc_o[mt][nt][r] *= alpha[mt][r>>1];
        __syncthreads();
        if (wn == 0 && t4 == 0){
            #pragma unroll
            for (int mt=0; mt<4; mt++)
                #pragma unroll
                for (int hf=0; hf<2; hf++){
                    int row = wm*64 + mt*16 + tg + hf*8;
                    float rs = red[row] + red[128+row] + red[256+row] + red[384+row];
                    l_s[row] = l_s[row]*alpha[mt][hf] + rs;
                    m_s[row] = mnew[mt][hf];
                }
        }

        for (int kc=0; kc<2; kc++){
            if (kc==0) { CP_WAIT(1); } else { CP_WAIT(0); }
            __syncthreads();
            int stg = kc*STG_BYTES;
            uint32_t pb = FA_P + kc*16384;
            #pragma unroll
            for (int ks=0; ks<4; ks++){
                uint32_t bh[8][2], bl[8][2];
                #pragma unroll
                for (int g=0; g<4; g++){
                    int row = wn*64 + g*16 + (lid&7) + ((lid>>4)&1)*8;
                    int cb2 = ks*32 + ((lid>>3)&1)*16;
                    uint32_t off = SWZ(row*128 + cb2);
                    uint32_t r0,r1,r2,r3;
                    ldm_x4(r0,r1,r2,r3, sb+stg+off);
                    bh[2*g][0]=r0; bh[2*g][1]=r1; bh[2*g+1][0]=r2; bh[2*g+1][1]=r3;
                    ldm_x4(r0,r1,r2,r3, sb+stg+32768+off);
                    bl[2*g][0]=r0; bl[2*g][1]=r1; bl[2*g+1][0]=r2; bl[2*g+1][1]=r3;
                }
                #pragma unroll
                for (int mt=0; mt<4; mt++){
                    int row = wm*64 + mt*16 + (lid&15);
                    uint32_t colb = ks*32 + ((lid>>4)&1)*16;
                    uint32_t off = SWZ(row*128 + colb);
                    uint32_t ah[4], al[4];
                    ldm_x4(ah[0],ah[1],ah[2],ah[3], sb+pb+off);
                    ldm_x4(al[0],al[1],al[2],al[3], sb+pb+32768+off);
                    #pragma unroll
                    for (int nt=0;nt<8;nt++){
                        mma16816(acc_o[mt][nt], ah, bh[nt]);
                        mma16816(acc_o[mt][nt], ah, bl[nt]);
                        mma16816(acc_o[mt][nt], al, bh[nt]);
                    }
                }
            }
            __syncthreads();
        }
    }

    __syncthreads();
    float* AOp = AO + (size_t)bb*S_*E_ + hh*D_;
    #pragma unroll
    for (int mt=0; mt<4; mt++)
        #pragma unroll
        for (int hf=0; hf<2; hf++){
            int row = wm*64 + mt*16 + tg + hf*8;
            float linv = 1.f/l_s[row];
            #pragma unroll
            for (int nt=0; nt<8; nt++){
                int col = wn*64 + nt*8 + t4*2;
                float2 v;
                v.x = acc_o[mt][nt][hf*2+0]*linv;
                v.y = acc_o[mt][nt][hf*2+1]*linv;
                *(float2*)(AOp + (size_t)(m0+row)*E_ + col) = v;
            }
        }
}

// ================= small kernels =================
__global__ void split_f32(const float* __restrict__ src, bf16* __restrict__ h, bf16* __restrict__ l, int n4){
    int i = blockIdx.x*blockDim.x + threadIdx.x;
    if (i >= n4) return;
    float4 v = ((const float4*)src)[i];
    size_t o = (size_t)i*4;
    store_split(h, l, o+0, v.x); store_split(h, l, o+1, v.y);
    store_split(h, l, o+2, v.z); store_split(h, l, o+3, v.w);
}

__global__ void transW(const float* __restrict__ W, bf16* __restrict__ Th, bf16* __restrict__ Tl){
    __shared__ float t[32][33];
    int k0 = blockIdx.x*32, n0 = blockIdx.y*32;
    int tx = threadIdx.x, ty = threadIdx.y;
    #pragma unroll
    for (int i=0;i<32;i+=8) t[ty+i][tx] = W[(size_t)(k0+ty+i)*E_ + n0+tx];
    __syncthreads();
    #pragma unroll
    for (int i=0;i<32;i+=8){
        size_t o = (size_t)(n0+ty+i)*E_ + k0+tx;
        store_split(Th, Tl, o, t[tx][ty+i]);
    }
}

__global__ void transBH(const float* __restrict__ X, bf16* __restrict__ Th, bf16* __restrict__ Tl){
    __shared__ float t[32][33];
    int z = blockIdx.z, b = z / H_, h = z % H_;
    int s0 = blockIdx.x*32, d0 = blockIdx.y*32;
    int tx = threadIdx.x, ty = threadIdx.y;
    const float* src = X + (size_t)b*S_*E_ + h*D_;
    #pragma unroll
    for (int i=0;i<32;i+=8) t[ty+i][tx] = src[(size_t)(s0+ty+i)*E_ + d0+tx];
    __syncthreads();
    #pragma unroll
    for (int i=0;i<32;i+=8){
        size_t o = (size_t)z*D_*S_ + (size_t)(d0+ty+i)*S_ + s0+tx;
        store_split(Th, Tl, o, t[tx][ty+i]);
    }
}

__global__ void transMem(const float* __restrict__ M, bf16* __restrict__ Th, bf16* __restrict__ Tl){
    __shared__ float t[32][33];
    int h = blockIdx.z;
    int d0 = blockIdx.x*32, e0 = blockIdx.y*32;
    int tx = threadIdx.x, ty = threadIdx.y;
    #pragma unroll
    for (int i=0;i<32;i+=8) t[ty+i][tx] = M[(size_t)h*D_*D_ + (size_t)(d0+ty+i)*D_ + e0+tx];
    __syncthreads();
    #pragma unroll
    for (int i=0;i<32;i+=8){
        size_t o = (size_t)h*D_*D_ + (size_t)(e0+ty+i)*D_ + d0+tx;
        store_split(Th, Tl, o, t[tx][ty+i]);
    }
}

__global__ void rowdot_split(const bf16* __restrict__ Hh, const bf16* __restrict__ Hl,
                             const float* __restrict__ zvec, float* __restrict__ out){
    int w = threadIdx.x >> 5, lane = threadIdx.x & 31;
    int r = blockIdx.x*8 + w;
    int z = r / S_, s = r % S_;
    int b = z / H_, h = z % H_;
    size_t base = (size_t)(b*S_+s)*E_ + h*D_;
    const float* zp = zvec + h*D_;
    float acc = 0.f;
    #pragma unroll
    for (int d=lane; d<D_; d+=32)
        acc += (__bfloat162float(Hh[base+d]) + __bfloat162float(Hl[base+d])) * zp[d];
    #pragma unroll
    for (int o=16;o;o>>=1) acc += __shfl_xor_sync(0xffffffffu, acc, o);
    if (lane==0) out[r] = acc;
}

__global__ void znew_part(const float* __restrict__ SK, float* __restrict__ part){
    int z = blockIdx.x, c = blockIdx.y;
    int b = z / H_, h = z % H_;
    int d = threadIdx.x;
    const float* p = SK + (size_t)b*S_*E_ + h*D_ + d + (size_t)(c*256)*E_;
    float acc = 0.f;
    #pragma unroll 8
    for (int s=0; s<256; s++) acc += p[(size_t)s*E_];
    part[(z*8+c)*D_ + d] = acc;
}
__global__ void znew_fin(const float* __restrict__ part, const float* __restrict__ zvec,
                         float* __restrict__ out){
    int z = blockIdx.x, d = threadIdx.x;
    float a = zvec[(z%H_)*D_ + d];
    #pragma unroll
    for (int c=0;c<8;c++) a += part[(z*8+c)*D_ + d];
    out[z*D_ + d] = a;
}

// ================= launch =================
extern "C" void kernel_launch(void* const* d_in, const int* in_sizes, int n_in,
                              void* d_out, int out_size)
{
    const float* hs    = (const float*)d_in[0];
    const float* Wq    = (const float*)d_in[1];
    const float* Wk    = (const float*)d_in[2];
    const float* Wv    = (const float*)d_in[3];
    const float* Wo    = (const float*)d_in[4];
    const float* bo    = (const float*)d_in[5];
    const float* betas = (const float*)d_in[6];
    const float* memp  = (const float*)d_in[7];
    const float* zv    = (const float*)d_in[8];
    float* out = (float*)d_out;

    cudaFuncSetAttribute(tc_gemm, cudaFuncAttributeMaxDynamicSharedMemorySize, G5_SMEM);
    cudaFuncSetAttribute(fa_kernel, cudaFuncAttributeMaxDynamicSharedMemorySize, FA_SMEM);

#define GS(var, sym) cudaGetSymbolAddress((void**)&var, sym)
    bf16 *HSh,*HSl,*WqTh,*WqTl,*WkTh,*WkTl,*WvTh,*WvTl,*WoTh,*WoTl,*memTh,*memTl;
    bf16 *Qh,*Ql,*Kh,*Kl,*SQh,*SQl,*SKh,*SKl,*ABh,*ABl,*VTh,*VTl,*UTh,*UTl,*SKTh,*SKTl;
    float *Vf,*Uf,*SKf,*AO,*Zq,*Zk,*Zp;
    GS(HSh,g_HSh); GS(HSl,g_HSl);
    GS(WqTh,g_WqTh); GS(WqTl,g_WqTl); GS(WkTh,g_WkTh); GS(WkTl,g_WkTl);
    GS(WvTh,g_WvTh); GS(WvTl,g_WvTl); GS(WoTh,g_WoTh); GS(WoTl,g_WoTl);
    GS(memTh,g_memTh); GS(memTl,g_memTl);
    GS(Qh,g_Qh); GS(Ql,g_Ql); GS(Kh,g_Kh); GS(Kl,g_Kl);
    GS(SQh,g_SQh); GS(SQl,g_SQl); GS(SKh,g_SKh); GS(SKl,g_SKl);
    GS(ABh,g_ABh); GS(ABl,g_ABl);
    GS(VTh,g_VTh); GS(VTl,g_VTl); GS(UTh,g_UTh); GS(UTl,g_UTl);
    GS(SKTh,g_SKTh); GS(SKTl,g_SKTl);
    GS(Vf,g_Vf); GS(Uf,g_Uf); GS(SKf,g_SKf); GS(AO,g_AO);
    GS(Zq,g_Zq); GS(Zk,g_Zk); GS(Zp,g_Zpart);

    const long OUT_MEM = (long)B_*S_*E_;
    const long OUT_Z   = OUT_MEM + (long)B_*H_*D_*D_;
    dim3 t256(256), t512(512), t328(32,8);

    // input conversions
    split_f32<<<MSZ/1024, t256>>>(hs, HSh, HSl, MSZ/4);
    transW<<<dim3(32,32), t328>>>(Wq, WqTh, WqTl);
    transW<<<dim3(32,32), t328>>>(Wk, WkTh, WkTl);
    transW<<<dim3(32,32), t328>>>(Wv, WvTh, WvTl);
    transW<<<dim3(32,32), t328>>>(Wo, WoTh, WoTl);
    transMem<<<dim3(8,8,H_), t328>>>(memp, memTh, memTl);

    // projections (N tiles of 256)
    tc_gemm<<<dim3(4,64,1), t512, G5_SMEM>>>(HSh,HSl,WqTh,WqTl, E_,E_,E_,E_,
        0,0,0,0,0,0, EP_SIGQK, 0, Qh,Ql, SQh,SQl, 0,0,0,0);
    tc_gemm<<<dim3(4,64,1), t512, G5_SMEM>>>(HSh,HSl,WkTh,WkTl, E_,E_,E_,E_,
        0,0,0,0,0,0, EP_SIGQK, SKf, Kh,Kl, SKh,SKl, 0,0,0,0);
    tc_gemm<<<dim3(4,64,1), t512, G5_SMEM>>>(HSh,HSl,WvTh,WvTl, E_,E_,E_,E_,
        0,0,0,0,0,0, EP_F32, Vf, 0,0,0,0, 0,0,0,0);

    transBH<<<dim3(64,8,BH_), t328>>>(Vf, VTh, VTl);

    // fused attention
    fa_kernel<<<256, t256, FA_SMEM>>>(Qh,Ql,Kh,Kl,VTh,VTl, AO);

    // sigma . z
    rowdot_split<<<BH_*S_/8, t256>>>(SQh, SQl, zv, Zq);
    rowdot_split<<<BH_*S_/8, t256>>>(SKh, SKl, zv, Zk);

    // A_mem + gate mix -> split AB  (N=256: one n-tile)
    tc_gemm<<<dim3(1,16,BH_), t512, G5_SMEM>>>(SQh,SQl,memTh,memTl, D_, E_,D_,E_,
        (long)S_*E_, D_, 0, (long)D_*D_, (long)S_*E_, (long)D_,
        EP_AMEM, 0, ABh,ABl, 0,0, Zq, AO, betas, 0);

    // U = V - delta
    tc_gemm<<<dim3(1,16,BH_), t512, G5_SMEM>>>(SKh,SKl,memTh,memTl, D_, E_,D_,E_,
        (long)S_*E_, D_, 0, (long)D_*D_, (long)S_*E_, (long)D_,
        EP_DELTA, Uf, 0,0,0,0, Zk, Vf, 0, 0);

    transBH<<<dim3(64,8,BH_), t328>>>(Uf, UTh, UTl);
    transBH<<<dim3(64,8,BH_), t328>>>(SKf, SKTh, SKTl);

    // mem_new = mem + SK^T @ U   (M=256 -> 2 m-tiles, N=256)
    tc_gemm<<<dim3(1,2,BH_), t512, G5_SMEM>>>(SKTh,SKTl,UTh,UTl, S_, S_,S_,D_,
        (long)H_*D_*S_, (long)D_*S_, (long)H_*D_*S_, (long)D_*S_, (long)H_*D_*D_, (long)D_*D_,
        EP_MEMUPD, out+OUT_MEM, 0,0,0,0, 0, memp, 0, 0);

    // z_new
    znew_part<<<dim3(BH_,8), D_>>>(SKf, Zp);
    znew_fin<<<BH_, D_>>>(Zp, zv, out+OUT_Z);

    // out projection + bias
    tc_gemm<<<dim3(4,64,1), t512, G5_SMEM>>>(ABh,ABl,WoTh,WoTl, E_,E_,E_,E_,
        0,0,0,0,0,0, EP_BIAS, out, 0,0,0,0, 0,0,0, bo);
}